// round 8
// baseline (speedup 1.0000x reference)
#include <cuda_runtime.h>
#include <cuda_bf16.h>
#include <cstdint>
#include <cstddef>

// smem layout (bytes, base-relative)
//  A  region: 0 .. 86016       x (ST_X) pass1 / e (ST_E) pass1 / xi (ST_E) pass2; lo at +43008 / +34816
//  CB0:       86016 .. 122880  weight chunk buf (hi 18432 | lo 18432)
//  CB1:       122880 .. 159744
//  S:         159744 .. 227328 fp32 S [128][132] (pass 2 only)
//  F2:        227328 .. 229376 f2 partial buffer
#define CB0_OFF 86016u
#define CB1_OFF 122880u
#define S_OFF   159744u
#define F2_OFF  227328u
#define SMEM_TOTAL 229376
#define ST_X 336      // x row stride bytes (168 bf16)
#define ST_E 272      // e/xi row stride bytes (136 bf16)
#define ST_W 144      // weight chunk row stride bytes (72 bf16)
#define CHUNK_B 36864
#define NCHUNKS 72    // pass1: 8 agents * 7 (3 wg + 2 wv + 2 f1b); pass2: 8 * 2 f1a

// ---------------------------------------------------------------- helpers
__device__ __forceinline__ uint32_t smem_to_u32(const void* p) {
    uint32_t a;
    asm("{ .reg .u64 t; cvta.to.shared.u64 t, %1; cvt.u32.u64 %0, t; }"
        : "=r"(a) : "l"(p));
    return a;
}
__device__ __forceinline__ float lrelu(float x) { return x > 0.f ? x : 0.01f * x; }
__device__ __forceinline__ uint32_t pk(__nv_bfloat16 a, __nv_bfloat16 b) {
    __nv_bfloat162 t; t.x = a; t.y = b;
    return *reinterpret_cast<uint32_t*>(&t);
}
__device__ __forceinline__ void sp2(float a, float b, uint32_t& h, uint32_t& l) {
    __nv_bfloat16 h0 = __float2bfloat16(a), h1 = __float2bfloat16(b);
    __nv_bfloat16 l0 = __float2bfloat16(a - __bfloat162float(h0));
    __nv_bfloat16 l1 = __float2bfloat16(b - __bfloat162float(h1));
    h = pk(h0, h1); l = pk(l0, l1);
}

#define LDSM4(r, a) \
    asm volatile("ldmatrix.sync.aligned.m8n8.x4.shared.b16 {%0,%1,%2,%3}, [%4];" \
        : "=r"((r)[0]), "=r"((r)[1]), "=r"((r)[2]), "=r"((r)[3]) : "r"(a))

#define MMA(c, av, b0, b1) \
    asm volatile("mma.sync.aligned.m16n8k16.row.col.f32.bf16.bf16.f32 " \
        "{%0,%1,%2,%3},{%4,%5,%6,%7},{%8,%9},{%0,%1,%2,%3};" \
        : "+f"((c)[0]), "+f"((c)[1]), "+f"((c)[2]), "+f"((c)[3]) \
        : "r"((av)[0]), "r"((av)[1]), "r"((av)[2]), "r"((av)[3]), "r"(b0), "r"(b1))

#define CPWAIT1() asm volatile("cp.async.wait_group 1;" ::: "memory")
#define CPWAIT0() asm volatile("cp.async.wait_group 0;" ::: "memory")
#define CPCOMMIT() asm volatile("cp.async.commit_group;" ::: "memory")

// ------------------------------------------------------------------- scratch
__device__ __align__(16) char g_wg[8 * 110592];     // per agent: 3 chunks (hi|lo 18432 each)
__device__ __align__(16) char g_wv[73728];          // 2 chunks
__device__ __align__(16) char g_wf1[8 * 147456];    // per agent: f1a c0,c1 | f1b c0,c1
__device__ __align__(16) char g_vscr[268435456];    // 512 tiles x 8 agents x 65536 fp32 v
__device__ __align__(16) char g_pscr[268435456];    // 512 tiles x 8 agents x 65536 fp32 p=Wf1b*e

// --------------------------------------------------------------- prep kernel
#define NWG (8 * 160 * 128)
#define NWV (128 * 128)
#define NWF (8 * 256 * 128)
#define NPREP (NWG + NWV + NWF)

__global__ void prep_kernel(const float* __restrict__ Wg,
                            const float* __restrict__ Wv,
                            const float* __restrict__ Wf1) {
    int i = blockIdx.x * blockDim.x + threadIdx.x;
    if (i >= NPREP) return;
    float v; char* base; int n, k;
    if (i < NWG) {
        int a = i / 20480, r = i - a * 20480;
        k = r >> 7; n = r & 127;
        v = Wg[(size_t)a * 20480 + (size_t)k * 128 + n];
        base = g_wg + (size_t)a * 110592 + (size_t)(k >> 6) * CHUNK_B;
    } else if (i < NWG + NWV) {
        int t = i - NWG;
        k = t >> 7; n = t & 127;
        v = Wv[(size_t)(n >> 5) * 4096 + (size_t)k * 32 + (n & 31)];
        base = g_wv + (size_t)(k >> 6) * CHUNK_B;
    } else {
        int t = i - NWG - NWV;
        int a = t >> 15, r = t & 32767;
        int ii = r >> 7; n = r & 127;
        int p = ii >> 7; k = ii & 127;
        v = Wf1[(size_t)a * 32768 + (size_t)ii * 128 + n];
        base = g_wf1 + (size_t)a * 147456 + (size_t)(p * 2 + (k >> 6)) * CHUNK_B;
    }
    int kk = k & 63;
    __nv_bfloat16 h = __float2bfloat16(v);
    __nv_bfloat16 l = __float2bfloat16(v - __bfloat162float(h));
    *(__nv_bfloat16*)(base + (size_t)n * ST_W + kk * 2) = h;
    *(__nv_bfloat16*)(base + 18432 + (size_t)n * ST_W + kk * 2) = l;
}

// ---------------------------------------------------------- chunk pipeline
__device__ __forceinline__ const char* chunk_src(int i) {
    if (i < 56) {
        int a = i / 7, c = i - a * 7;
        if (c < 3) return g_wg + (size_t)a * 110592 + (size_t)c * CHUNK_B;
        if (c < 5) return g_wv + (size_t)(c - 3) * CHUNK_B;
        return g_wf1 + (size_t)a * 147456 + (size_t)(c - 3) * CHUNK_B;  // c-5+2
    }
    int j = i - 56;
    int a = j >> 1, c = j & 1;
    return g_wf1 + (size_t)a * 147456 + (size_t)c * CHUNK_B;
}

__device__ __forceinline__ void prefetch_chunk(uint32_t sb, int idx, int tid) {
    const char* s = chunk_src(idx) + (size_t)tid * 16;
    uint32_t d = sb + ((idx & 1) ? CB1_OFF : CB0_OFF) + (uint32_t)tid * 16u;
#pragma unroll
    for (int i = 0; i < 9; i++) {
        asm volatile("cp.async.cg.shared.global [%0], [%1], 16;"
                     :: "r"(d + (uint32_t)i * 4096u), "l"(s + (size_t)i * 4096)
                     : "memory");
    }
    CPCOMMIT();
}

// ---------------------------------------------- pipelined fragment GEMM
struct Frag { uint32_t ah[4][4], al[4][4], bh[2][4], bl[2][4]; };

__device__ __forceinline__ void load_frags(Frag& f, uint32_t sb, uint32_t aHi,
        uint32_t aLo, int aStr, uint32_t bOff, int ks, int kbase,
        uint32_t aRow, uint32_t bRow, uint32_t colo) {
    uint32_t coA = (uint32_t)(kbase + ks) * 32 + colo;
    uint32_t coB = (uint32_t)ks * 32 + colo;
#pragma unroll
    for (int im = 0; im < 4; im++) {
        uint32_t r = (aRow + im * 16) * (uint32_t)aStr + coA;
        LDSM4(f.ah[im], sb + aHi + r);
        LDSM4(f.al[im], sb + aLo + r);
    }
#pragma unroll
    for (int ip = 0; ip < 2; ip++) {
        uint32_t r = (bRow + ip * 16) * (uint32_t)ST_W + coB;
        LDSM4(f.bh[ip], sb + bOff + r);
        LDSM4(f.bl[ip], sb + bOff + 18432u + r);
    }
}

__device__ __forceinline__ void mma_frags(Frag& f, float (&acc)[4][4][4]) {
#pragma unroll
    for (int im = 0; im < 4; im++)
#pragma unroll
        for (int in = 0; in < 4; in++) {
            uint32_t b0h = f.bh[in >> 1][in & 1], b1h = f.bh[in >> 1][(in & 1) + 2];
            uint32_t b0l = f.bl[in >> 1][in & 1], b1l = f.bl[in >> 1][(in & 1) + 2];
            MMA(acc[im][in], f.ah[im], b0h, b1h);
            MMA(acc[im][in], f.ah[im], b0l, b1l);
            MMA(acc[im][in], f.al[im], b0h, b1h);
        }
}

template<int NKS>
__device__ __forceinline__ void gemm_chunk_t(uint32_t sb, uint32_t aHi, uint32_t aLo,
        int aStr, uint32_t bOff, int kbase, float (&acc)[4][4][4], bool init,
        int wm, int wn, int lane) {
    if (init)
#pragma unroll
        for (int im = 0; im < 4; im++)
#pragma unroll
            for (int in = 0; in < 4; in++)
#pragma unroll
                for (int e = 0; e < 4; e++) acc[im][in][e] = 0.f;
    uint32_t aRow = (uint32_t)(wm * 64 + (lane & 15));
    uint32_t bRow = (uint32_t)(wn * 32 + (lane & 15));
    uint32_t colo = (uint32_t)((lane >> 4) * 16);
    Frag fr[2];
    load_frags(fr[0], sb, aHi, aLo, aStr, bOff, 0, kbase, aRow, bRow, colo);
#pragma unroll
    for (int ks = 0; ks < NKS; ks++) {
        if (ks + 1 < NKS)
            load_frags(fr[(ks + 1) & 1], sb, aHi, aLo, aStr, bOff, ks + 1, kbase,
                       aRow, bRow, colo);
        mma_frags(fr[ks & 1], acc);
    }
}

template<int NKS>
__device__ __forceinline__ void consume_t(uint32_t sb, int& cc, int& pc,
        uint32_t aHi, uint32_t aLo, int aStr, int kbase, float (&acc)[4][4][4],
        bool init, int wm, int wn, int lane, int tid) {
    if (pc - cc >= 2) CPWAIT1(); else CPWAIT0();
    __syncthreads();
    uint32_t bOff = (cc & 1) ? CB1_OFF : CB0_OFF;
    gemm_chunk_t<NKS>(sb, aHi, aLo, aStr, bOff, kbase, acc, init, wm, wn, lane);
    __syncthreads();
    if (pc < NCHUNKS) { prefetch_chunk(sb, pc, tid); pc++; }
    cc++;
}

// ----------------------------------------------------------------- main
__global__ __launch_bounds__(256, 1)
void critic_main(const float* __restrict__ obs, const float* __restrict__ act,
                 const float* __restrict__ bg, const float* __restrict__ bvv,
                 const float* __restrict__ bf1, const float* __restrict__ wf2,
                 const float* __restrict__ bf2, float* __restrict__ out) {
    extern __shared__ __align__(16) char sm[];
    uint32_t sb = smem_to_u32(sm);
    int tid = threadIdx.x;
    int lane = tid & 31, wid = tid >> 5;
    int wm = wid & 1, wn = wid >> 1;
    int g = lane >> 2, t4 = lane & 3;
    int tile = blockIdx.x;

    float acc[4][4][4];

    int cc = 0, pc = 0;
    prefetch_chunk(sb, pc, tid); pc++;
    prefetch_chunk(sb, pc, tid); pc++;

    // ============================ PASS 1 ============================
    for (int a = 0; a < 8; a++) {
        // x rows -> A region (split hi/lo). 2 threads per row.
        {
            int row = tid >> 1, half = tid & 1;
            size_t rb = (size_t)a * 65536 + (size_t)tile * 128 + row;
            const float4* op = (const float4*)(obs + rb * 128) + half * 16;
            const float4* ap = (const float4*)(act + rb * 32) + half * 4;
            char* hb = sm + (size_t)row * ST_X;
            char* lb = hb + 43008;
#pragma unroll 4
            for (int i = 0; i < 16; i++) {
                float4 f = __ldg(op + i);
                int k = half * 64 + i * 4;
                uint32_t h0, l0, h1, l1;
                sp2(f.x, f.y, h0, l0); sp2(f.z, f.w, h1, l1);
                *(uint2*)(hb + k * 2) = make_uint2(h0, h1);
                *(uint2*)(lb + k * 2) = make_uint2(l0, l1);
            }
#pragma unroll
            for (int i = 0; i < 4; i++) {
                float4 f = __ldg(ap + i);
                int k = 128 + half * 16 + i * 4;
                uint32_t h0, l0, h1, l1;
                sp2(f.x, f.y, h0, l0); sp2(f.z, f.w, h1, l1);
                *(uint2*)(hb + k * 2) = make_uint2(h0, h1);
                *(uint2*)(lb + k * 2) = make_uint2(l0, l1);
            }
        }
        // g GEMM: K=160
        consume_t<4>(sb, cc, pc, 0u, 43008u, ST_X, 0, acc, true,  wm, wn, lane, tid);
        consume_t<4>(sb, cc, pc, 0u, 43008u, ST_X, 4, acc, false, wm, wn, lane, tid);
        consume_t<2>(sb, cc, pc, 0u, 43008u, ST_X, 8, acc, false, wm, wn, lane, tid);

        // e = lrelu(acc + bg) -> A region (ST_E image)
        {
            const float* bga = bg + a * 128;
#pragma unroll
            for (int im = 0; im < 4; im++)
#pragma unroll
                for (int in = 0; in < 4; in++) {
                    int c = wn * 32 + in * 8 + t4 * 2;
                    int r0 = wm * 64 + im * 16 + g;
                    float b0 = __ldg(bga + c), b1 = __ldg(bga + c + 1);
                    uint32_t h, l;
                    sp2(lrelu(acc[im][in][0] + b0), lrelu(acc[im][in][1] + b1), h, l);
                    *(uint32_t*)(sm + (size_t)r0 * ST_E + c * 2) = h;
                    *(uint32_t*)(sm + 34816 + (size_t)r0 * ST_E + c * 2) = l;
                    sp2(lrelu(acc[im][in][2] + b0), lrelu(acc[im][in][3] + b1), h, l);
                    *(uint32_t*)(sm + (size_t)(r0 + 8) * ST_E + c * 2) = h;
                    *(uint32_t*)(sm + 34816 + (size_t)(r0 + 8) * ST_E + c * 2) = l;
                }
        }
        // v GEMM: K=128 (A = e)
        consume_t<4>(sb, cc, pc, 0u, 34816u, ST_E, 0, acc, true,  wm, wn, lane, tid);
        consume_t<4>(sb, cc, pc, 0u, 34816u, ST_E, 4, acc, false, wm, wn, lane, tid);
        // v = lrelu(acc + bv) -> v scratch (fp32)
        {
            float* vdst = (float*)(g_vscr + ((size_t)tile * 8 + a) * 65536);
#pragma unroll
            for (int im = 0; im < 4; im++)
#pragma unroll
                for (int in = 0; in < 4; in++) {
                    int c = wn * 32 + in * 8 + t4 * 2;
                    int r0 = wm * 64 + im * 16 + g;
                    float b0 = __ldg(bvv + c), b1 = __ldg(bvv + c + 1);
                    *(float2*)(vdst + (size_t)r0 * 128 + c) =
                        make_float2(lrelu(acc[im][in][0] + b0), lrelu(acc[im][in][1] + b1));
                    *(float2*)(vdst + (size_t)(r0 + 8) * 128 + c) =
                        make_float2(lrelu(acc[im][in][2] + b0), lrelu(acc[im][in][3] + b1));
                }
        }
        // p GEMM: p = Wf1b * e, K=128 (A = e, still resident)
        consume_t<4>(sb, cc, pc, 0u, 34816u, ST_E, 0, acc, true,  wm, wn, lane, tid);
        consume_t<4>(sb, cc, pc, 0u, 34816u, ST_E, 4, acc, false, wm, wn, lane, tid);
        // p -> p scratch (raw fp32)
        {
            float* pdst = (float*)(g_pscr + ((size_t)tile * 8 + a) * 65536);
#pragma unroll
            for (int im = 0; im < 4; im++)
#pragma unroll
                for (int in = 0; in < 4; in++) {
                    int c = wn * 32 + in * 8 + t4 * 2;
                    int r0 = wm * 64 + im * 16 + g;
                    *(float2*)(pdst + (size_t)r0 * 128 + c) =
                        make_float2(acc[im][in][0], acc[im][in][1]);
                    *(float2*)(pdst + (size_t)(r0 + 8) * 128 + c) =
                        make_float2(acc[im][in][2], acc[im][in][3]);
                }
        }
    }

    // ============================ PASS 2 ============================
    // Build S = sum_a v_a in smem (fp32, padded stride 132 floats)
    {
        const float* vb = (const float*)(g_vscr + (size_t)tile * 8 * 65536);
        for (int j = tid * 4; j < 16384; j += 1024) {
            float4 s = make_float4(0.f, 0.f, 0.f, 0.f);
#pragma unroll
            for (int a = 0; a < 8; a++) {
                float4 v = __ldg((const float4*)(vb + (size_t)a * 16384 + j));
                s.x += v.x; s.y += v.y; s.z += v.z; s.w += v.w;
            }
            int r = j >> 7, c = j & 127;
            *(float4*)(sm + S_OFF + (size_t)r * 528 + c * 4) = s;
        }
    }
    __syncthreads();

    for (int a = 0; a < 8; a++) {
        // xi = S - v -> A region (ST_E image)
        {
            const float* vsrc = (const float*)(g_vscr + ((size_t)tile * 8 + a) * 65536);
            const float* Sp = (const float*)(sm + S_OFF);
#pragma unroll
            for (int im = 0; im < 4; im++)
#pragma unroll
                for (int in = 0; in < 4; in++) {
                    int c = wn * 32 + in * 8 + t4 * 2;
                    int r0 = wm * 64 + im * 16 + g;
                    float2 va = __ldg((const float2*)(vsrc + (size_t)r0 * 128 + c));
                    float2 vb2 = __ldg((const float2*)(vsrc + (size_t)(r0 + 8) * 128 + c));
                    float s0 = Sp[r0 * 132 + c], s1 = Sp[r0 * 132 + c + 1];
                    float s2 = Sp[(r0 + 8) * 132 + c], s3 = Sp[(r0 + 8) * 132 + c + 1];
                    uint32_t h, l;
                    sp2(s0 - va.x, s1 - va.y, h, l);
                    *(uint32_t*)(sm + (size_t)r0 * ST_E + c * 2) = h;
                    *(uint32_t*)(sm + 34816 + (size_t)r0 * ST_E + c * 2) = l;
                    sp2(s2 - vb2.x, s3 - vb2.y, h, l);
                    *(uint32_t*)(sm + (size_t)(r0 + 8) * ST_E + c * 2) = h;
                    *(uint32_t*)(sm + 34816 + (size_t)(r0 + 8) * ST_E + c * 2) = l;
                }
        }
        // f1a GEMM: h1_pre = Wf1a * xi, K=128
        consume_t<4>(sb, cc, pc, 0u, 34816u, ST_E, 0, acc, true,  wm, wn, lane, tid);
        consume_t<4>(sb, cc, pc, 0u, 34816u, ST_E, 4, acc, false, wm, wn, lane, tid);

        // f2: qv = bf2 + sum_c lrelu(h1_pre + p + bf1) * wf2
        {
            const float* psrc = (const float*)(g_pscr + ((size_t)tile * 8 + a) * 65536);
            float part[8];
#pragma unroll
            for (int i = 0; i < 8; i++) part[i] = 0.f;
            const float* b1a = bf1 + a * 128;
            const float* w2a = wf2 + a * 128;
#pragma unroll
            for (int im = 0; im < 4; im++)
#pragma unroll
                for (int in = 0; in < 4; in++) {
                    int c = wn * 32 + in * 8 + t4 * 2;
                    int r0 = wm * 64 + im * 16 + g;
                    float2 pa = __ldg((const float2*)(psrc + (size_t)r0 * 128 + c));
                    float2 pb = __ldg((const float2*)(psrc + (size_t)(r0 + 8) * 128 + c));
                    float b0 = __ldg(b1a + c), b1 = __ldg(b1a + c + 1);
                    float w0 = __ldg(w2a + c), w1 = __ldg(w2a + c + 1);
                    part[im * 2 + 0] += lrelu(acc[im][in][0] + pa.x + b0) * w0
                                      + lrelu(acc[im][in][1] + pa.y + b1) * w1;
                    part[im * 2 + 1] += lrelu(acc[im][in][2] + pb.x + b0) * w0
                                      + lrelu(acc[im][in][3] + pb.y + b1) * w1;
                }
#pragma unroll
            for (int i = 0; i < 8; i++) {
                part[i] += __shfl_xor_sync(0xffffffffu, part[i], 1);
                part[i] += __shfl_xor_sync(0xffffffffu, part[i], 2);
            }
            if (t4 == 0) {
#pragma unroll
                for (int i = 0; i < 8; i++) {
                    int row = wm * 64 + (i >> 1) * 16 + g + (i & 1) * 8;
                    ((float*)(sm + F2_OFF))[row * 4 + wn] = part[i];
                }
            }
            __syncthreads();
            if (tid < 128) {
                const float* bp = (const float*)(sm + F2_OFF) + tid * 4;
                float qv = __ldg(bf2 + a) + bp[0] + bp[1] + bp[2] + bp[3];
                out[(size_t)a * 65536 + (size_t)tile * 128 + tid] = qv;
            }
            __syncthreads();
        }
    }
}

// ------------------------------------------------------------------ launcher
extern "C" void kernel_launch(void* const* d_in, const int* in_sizes, int n_in,
                              void* d_out, int out_size) {
    const float* obs = (const float*)d_in[0];
    const float* act = (const float*)d_in[1];
    const float* Wg  = (const float*)d_in[2];
    const float* bg  = (const float*)d_in[3];
    // d_in[4]=Wq, d_in[5]=Wk: dead (softmax over size-1 axis == 1)
    const float* Wv  = (const float*)d_in[6];
    const float* bv  = (const float*)d_in[7];
    const float* Wf1 = (const float*)d_in[8];
    const float* bf1 = (const float*)d_in[9];
    const float* Wf2 = (const float*)d_in[10];
    const float* bf2 = (const float*)d_in[11];
    float* out = (float*)d_out;

    cudaFuncSetAttribute(critic_main, cudaFuncAttributeMaxDynamicSharedMemorySize,
                         SMEM_TOTAL);
    prep_kernel<<<(NPREP + 255) / 256, 256>>>(Wg, Wv, Wf1);
    critic_main<<<512, 256, SMEM_TOTAL>>>(obs, act, bg, bv, bf1, Wf2, bf2, out);
}

// round 9
// speedup vs baseline: 1.3256x; 1.3256x over previous
#include <cuda_runtime.h>
#include <cuda_bf16.h>
#include <cstdint>
#include <cstddef>

// smem layout (bytes, base-relative), Bt = 64 batch rows per CTA
//  A region: 0 .. 43008   x (ST_X: hi 0, lo 21504) / e,xi (ST_E: hi 0, lo 17408)
//            F2 partial buffer at 34816 (1 KB, pass2 only)
//  CB0: 43008 .. 63488    weight chunk (hi 10240 | lo 10240)
//  CB1: 63488 .. 83968
#define CB0_OFF 43008u
#define CB1_OFF 63488u
#define F2_OFF  34816u
#define SMEM_TOTAL 83968
#define ST_X 336      // x row stride bytes (168 bf16; 160 data)
#define ST_E 272      // e/xi row stride bytes (136 bf16)
#define ST_W 80       // weight chunk row stride bytes (40 bf16; 32 data)
#define CHUNK_B 20480 // hi 10240 | lo 10240 (128 rows x 32 kcols)
#define NCHUNKS 136   // pass1: 8*(5 wg + 4 wv + 4 f1b) = 104 ; pass2: 8*4 f1a = 32

// ---------------------------------------------------------------- helpers
__device__ __forceinline__ uint32_t smem_to_u32(const void* p) {
    uint32_t a;
    asm("{ .reg .u64 t; cvta.to.shared.u64 t, %1; cvt.u32.u64 %0, t; }"
        : "=r"(a) : "l"(p));
    return a;
}
__device__ __forceinline__ float lrelu(float x) { return x > 0.f ? x : 0.01f * x; }
__device__ __forceinline__ uint32_t pk(__nv_bfloat16 a, __nv_bfloat16 b) {
    __nv_bfloat162 t; t.x = a; t.y = b;
    return *reinterpret_cast<uint32_t*>(&t);
}
__device__ __forceinline__ void sp2(float a, float b, uint32_t& h, uint32_t& l) {
    __nv_bfloat16 h0 = __float2bfloat16(a), h1 = __float2bfloat16(b);
    __nv_bfloat16 l0 = __float2bfloat16(a - __bfloat162float(h0));
    __nv_bfloat16 l1 = __float2bfloat16(b - __bfloat162float(h1));
    h = pk(h0, h1); l = pk(l0, l1);
}

#define LDSM4(r, a) \
    asm volatile("ldmatrix.sync.aligned.m8n8.x4.shared.b16 {%0,%1,%2,%3}, [%4];" \
        : "=r"((r)[0]), "=r"((r)[1]), "=r"((r)[2]), "=r"((r)[3]) : "r"(a))

#define MMA(c, av, b0, b1) \
    asm volatile("mma.sync.aligned.m16n8k16.row.col.f32.bf16.bf16.f32 " \
        "{%0,%1,%2,%3},{%4,%5,%6,%7},{%8,%9},{%0,%1,%2,%3};" \
        : "+f"((c)[0]), "+f"((c)[1]), "+f"((c)[2]), "+f"((c)[3]) \
        : "r"((av)[0]), "r"((av)[1]), "r"((av)[2]), "r"((av)[3]), "r"(b0), "r"(b1))

#define CPWAIT1() asm volatile("cp.async.wait_group 1;" ::: "memory")
#define CPWAIT0() asm volatile("cp.async.wait_group 0;" ::: "memory")
#define CPCOMMIT() asm volatile("cp.async.commit_group;" ::: "memory")

// ------------------------------------------------------------------- scratch
__device__ __align__(16) char g_wg[8 * 102400];     // per agent: 5 chunks
__device__ __align__(16) char g_wv[81920];          // 4 chunks
__device__ __align__(16) char g_wf1[8 * 163840];    // per agent: f1a c0..3 | f1b c4..7
__device__ __align__(16) char g_vscr[268435456];    // 1024 tiles x 8 agents x 32768 fp32 v
__device__ __align__(16) char g_pscr[268435456];    // 1024 tiles x 8 agents x 32768 fp32 p=Wf1b*e

// --------------------------------------------------------------- prep kernel
#define NWG (8 * 160 * 128)
#define NWV (128 * 128)
#define NWF (8 * 256 * 128)
#define NPREP (NWG + NWV + NWF)

__global__ void prep_kernel(const float* __restrict__ Wg,
                            const float* __restrict__ Wv,
                            const float* __restrict__ Wf1) {
    int i = blockIdx.x * blockDim.x + threadIdx.x;
    if (i >= NPREP) return;
    float v; char* base; int n, k;
    if (i < NWG) {
        int a = i / 20480, r = i - a * 20480;
        k = r >> 7; n = r & 127;
        v = Wg[(size_t)a * 20480 + (size_t)k * 128 + n];
        base = g_wg + (size_t)a * 102400 + (size_t)(k >> 5) * CHUNK_B;
    } else if (i < NWG + NWV) {
        int t = i - NWG;
        k = t >> 7; n = t & 127;
        v = Wv[(size_t)(n >> 5) * 4096 + (size_t)k * 32 + (n & 31)];
        base = g_wv + (size_t)(k >> 5) * CHUNK_B;
    } else {
        int t = i - NWG - NWV;
        int a = t >> 15, r = t & 32767;
        int ii = r >> 7; n = r & 127;
        int p = ii >> 7; k = ii & 127;
        v = Wf1[(size_t)a * 32768 + (size_t)ii * 128 + n];
        base = g_wf1 + (size_t)a * 163840 + (size_t)(p * 4 + (k >> 5)) * CHUNK_B;
    }
    int kk = k & 31;
    __nv_bfloat16 h = __float2bfloat16(v);
    __nv_bfloat16 l = __float2bfloat16(v - __bfloat162float(h));
    *(__nv_bfloat16*)(base + (size_t)n * ST_W + kk * 2) = h;
    *(__nv_bfloat16*)(base + 10240 + (size_t)n * ST_W + kk * 2) = l;
}

// ---------------------------------------------------------- chunk pipeline
__device__ __forceinline__ const char* chunk_src(int i) {
    if (i < 104) {
        int a = i / 13, c = i - a * 13;
        if (c < 5) return g_wg + (size_t)a * 102400 + (size_t)c * CHUNK_B;
        if (c < 9) return g_wv + (size_t)(c - 5) * CHUNK_B;
        return g_wf1 + (size_t)a * 163840 + (size_t)(c - 5) * CHUNK_B;  // f1b chunks 4..7
    }
    int j = i - 104;
    int a = j >> 2, c = j & 3;
    return g_wf1 + (size_t)a * 163840 + (size_t)c * CHUNK_B;            // f1a chunks 0..3
}

__device__ __forceinline__ void prefetch_chunk(uint32_t sb, int idx, int tid) {
    const char* s = chunk_src(idx) + (size_t)tid * 16;
    uint32_t d = sb + ((idx & 1) ? CB1_OFF : CB0_OFF) + (uint32_t)tid * 16u;
#pragma unroll
    for (int i = 0; i < 5; i++) {
        asm volatile("cp.async.cg.shared.global [%0], [%1], 16;"
                     :: "r"(d + (uint32_t)i * 4096u), "l"(s + (size_t)i * 4096)
                     : "memory");
    }
    CPCOMMIT();
}

// ------------------------------------------------- warp-tile 32x32 GEMM
// per chunk: 2 k-steps, 3 split products (hh + hl + lh)
__device__ __forceinline__ void gemm_chunk(uint32_t sb, uint32_t aHi, uint32_t aLo,
        int aStr, uint32_t bOff, int kbase, float (&acc)[2][4][4], bool init,
        int wm, int wn, int lane) {
    if (init)
#pragma unroll
        for (int im = 0; im < 2; im++)
#pragma unroll
            for (int in = 0; in < 4; in++)
#pragma unroll
                for (int e = 0; e < 4; e++) acc[im][in][e] = 0.f;
    uint32_t aRow = (uint32_t)(wm * 32 + (lane & 15));
    uint32_t bRow = (uint32_t)(wn * 32 + (lane & 15));
    uint32_t colo = (uint32_t)((lane >> 4) * 16);
#pragma unroll
    for (int ks = 0; ks < 2; ks++) {
        uint32_t coA = (uint32_t)(kbase + ks) * 32 + colo;
        uint32_t coB = (uint32_t)ks * 32 + colo;
        uint32_t ah[2][4], al[2][4], bh[2][4], bl[2][4];
#pragma unroll
        for (int im = 0; im < 2; im++) {
            uint32_t r = (aRow + im * 16) * (uint32_t)aStr + coA;
            LDSM4(ah[im], sb + aHi + r);
            LDSM4(al[im], sb + aLo + r);
        }
#pragma unroll
        for (int ip = 0; ip < 2; ip++) {
            uint32_t r = (bRow + ip * 16) * (uint32_t)ST_W + coB;
            LDSM4(bh[ip], sb + bOff + r);
            LDSM4(bl[ip], sb + bOff + 10240u + r);
        }
#pragma unroll
        for (int im = 0; im < 2; im++)
#pragma unroll
            for (int in = 0; in < 4; in++) {
                uint32_t b0h = bh[in >> 1][in & 1], b1h = bh[in >> 1][(in & 1) + 2];
                uint32_t b0l = bl[in >> 1][in & 1], b1l = bl[in >> 1][(in & 1) + 2];
                MMA(acc[im][in], ah[im], b0h, b1h);
                MMA(acc[im][in], ah[im], b0l, b1l);
                MMA(acc[im][in], al[im], b0h, b1h);
            }
    }
}

__device__ __forceinline__ void consume(uint32_t sb, int& cc, int& pc,
        uint32_t aHi, uint32_t aLo, int aStr, int kbase, float (&acc)[2][4][4],
        bool init, int wm, int wn, int lane, int tid) {
    if (pc - cc >= 2) CPWAIT1(); else CPWAIT0();
    __syncthreads();
    uint32_t bOff = (cc & 1) ? CB1_OFF : CB0_OFF;
    gemm_chunk(sb, aHi, aLo, aStr, bOff, kbase, acc, init, wm, wn, lane);
    __syncthreads();
    if (pc < NCHUNKS) { prefetch_chunk(sb, pc, tid); pc++; }
    cc++;
}

// ----------------------------------------------------------------- main
__global__ __launch_bounds__(256, 2)
void critic_main(const float* __restrict__ obs, const float* __restrict__ act,
                 const float* __restrict__ bg, const float* __restrict__ bvv,
                 const float* __restrict__ bf1, const float* __restrict__ wf2,
                 const float* __restrict__ bf2, float* __restrict__ out) {
    extern __shared__ __align__(16) char sm[];
    uint32_t sb = smem_to_u32(sm);
    int tid = threadIdx.x;
    int lane = tid & 31, wid = tid >> 5;
    int wm = wid & 1, wn = wid >> 1;
    int g = lane >> 2, t4 = lane & 3;
    int tile = blockIdx.x;

    float acc[2][4][4];
    float S[2][4][4];

    int cc = 0, pc = 0;
    prefetch_chunk(sb, pc, tid); pc++;
    prefetch_chunk(sb, pc, tid); pc++;

    // ============================ PASS 1 ============================
    for (int a = 0; a < 8; a++) {
        // x rows -> A region (split hi/lo). 4 threads per row.
        {
            int row = tid >> 2, q = tid & 3;
            size_t rb = (size_t)a * 65536 + (size_t)tile * 64 + row;
            const float4* op = (const float4*)(obs + rb * 128) + q * 8;
            const float4* ap = (const float4*)(act + rb * 32) + q * 2;
            char* hb = sm + (size_t)row * ST_X;
            char* lb = hb + 21504;
#pragma unroll 4
            for (int i = 0; i < 8; i++) {
                float4 f = __ldg(op + i);
                int k = q * 32 + i * 4;
                uint32_t h0, l0, h1, l1;
                sp2(f.x, f.y, h0, l0); sp2(f.z, f.w, h1, l1);
                *(uint2*)(hb + k * 2) = make_uint2(h0, h1);
                *(uint2*)(lb + k * 2) = make_uint2(l0, l1);
            }
#pragma unroll
            for (int i = 0; i < 2; i++) {
                float4 f = __ldg(ap + i);
                int k = 128 + q * 8 + i * 4;
                uint32_t h0, l0, h1, l1;
                sp2(f.x, f.y, h0, l0); sp2(f.z, f.w, h1, l1);
                *(uint2*)(hb + k * 2) = make_uint2(h0, h1);
                *(uint2*)(lb + k * 2) = make_uint2(l0, l1);
            }
        }
        // g GEMM: K=160 = 5 chunks
#pragma unroll 1
        for (int c = 0; c < 5; c++)
            consume(sb, cc, pc, 0u, 21504u, ST_X, c * 2, acc, c == 0, wm, wn, lane, tid);

        // e = lrelu(acc + bg) -> A region (ST_E image)
        {
            const float* bga = bg + a * 128;
#pragma unroll
            for (int im = 0; im < 2; im++)
#pragma unroll
                for (int in = 0; in < 4; in++) {
                    int c = wn * 32 + in * 8 + t4 * 2;
                    int r0 = wm * 32 + im * 16 + g;
                    float b0 = __ldg(bga + c), b1 = __ldg(bga + c + 1);
                    uint32_t h, l;
                    sp2(lrelu(acc[im][in][0] + b0), lrelu(acc[im][in][1] + b1), h, l);
                    *(uint32_t*)(sm + (size_t)r0 * ST_E + c * 2) = h;
                    *(uint32_t*)(sm + 17408 + (size_t)r0 * ST_E + c * 2) = l;
                    sp2(lrelu(acc[im][in][2] + b0), lrelu(acc[im][in][3] + b1), h, l);
                    *(uint32_t*)(sm + (size_t)(r0 + 8) * ST_E + c * 2) = h;
                    *(uint32_t*)(sm + 17408 + (size_t)(r0 + 8) * ST_E + c * 2) = l;
                }
        }
        // v GEMM: K=128 = 4 chunks (A = e)
#pragma unroll 1
        for (int c = 0; c < 4; c++)
            consume(sb, cc, pc, 0u, 17408u, ST_E, c * 2, acc, c == 0, wm, wn, lane, tid);
        // v = lrelu(acc + bv): accumulate S in regs, store v to scratch
        {
            float* vdst = (float*)(g_vscr + ((size_t)tile * 8 + a) * 32768);
#pragma unroll
            for (int im = 0; im < 2; im++)
#pragma unroll
                for (int in = 0; in < 4; in++) {
                    int c = wn * 32 + in * 8 + t4 * 2;
                    int r0 = wm * 32 + im * 16 + g;
                    float b0 = __ldg(bvv + c), b1 = __ldg(bvv + c + 1);
                    float v0 = lrelu(acc[im][in][0] + b0), v1 = lrelu(acc[im][in][1] + b1);
                    float v2 = lrelu(acc[im][in][2] + b0), v3 = lrelu(acc[im][in][3] + b1);
                    if (a == 0) {
                        S[im][in][0] = v0; S[im][in][1] = v1;
                        S[im][in][2] = v2; S[im][in][3] = v3;
                    } else {
                        S[im][in][0] += v0; S[im][in][1] += v1;
                        S[im][in][2] += v2; S[im][in][3] += v3;
                    }
                    *(float2*)(vdst + (size_t)r0 * 128 + c) = make_float2(v0, v1);
                    *(float2*)(vdst + (size_t)(r0 + 8) * 128 + c) = make_float2(v2, v3);
                }
        }
        // p GEMM: p = Wf1b * e, K=128 (A = e, still resident)
#pragma unroll 1
        for (int c = 0; c < 4; c++)
            consume(sb, cc, pc, 0u, 17408u, ST_E, c * 2, acc, c == 0, wm, wn, lane, tid);
        // p -> scratch (raw fp32)
        {
            float* pdst = (float*)(g_pscr + ((size_t)tile * 8 + a) * 32768);
#pragma unroll
            for (int im = 0; im < 2; im++)
#pragma unroll
                for (int in = 0; in < 4; in++) {
                    int c = wn * 32 + in * 8 + t4 * 2;
                    int r0 = wm * 32 + im * 16 + g;
                    *(float2*)(pdst + (size_t)r0 * 128 + c) =
                        make_float2(acc[im][in][0], acc[im][in][1]);
                    *(float2*)(pdst + (size_t)(r0 + 8) * 128 + c) =
                        make_float2(acc[im][in][2], acc[im][in][3]);
                }
        }
    }

    // ============================ PASS 2 ============================
    for (int a = 0; a < 8; a++) {
        // xi = S - v -> A region (ST_E image)
        {
            const float* vsrc = (const float*)(g_vscr + ((size_t)tile * 8 + a) * 32768);
#pragma unroll
            for (int im = 0; im < 2; im++)
#pragma unroll
                for (int in = 0; in < 4; in++) {
                    int c = wn * 32 + in * 8 + t4 * 2;
                    int r0 = wm * 32 + im * 16 + g;
                    float2 va = __ldg((const float2*)(vsrc + (size_t)r0 * 128 + c));
                    float2 vb = __ldg((const float2*)(vsrc + (size_t)(r0 + 8) * 128 + c));
                    uint32_t h, l;
                    sp2(S[im][in][0] - va.x, S[im][in][1] - va.y, h, l);
                    *(uint32_t*)(sm + (size_t)r0 * ST_E + c * 2) = h;
                    *(uint32_t*)(sm + 17408 + (size_t)r0 * ST_E + c * 2) = l;
                    sp2(S[im][in][2] - vb.x, S[im][in][3] - vb.y, h, l);
                    *(uint32_t*)(sm + (size_t)(r0 + 8) * ST_E + c * 2) = h;
                    *(uint32_t*)(sm + 17408 + (size_t)(r0 + 8) * ST_E + c * 2) = l;
                }
        }
        // f1a GEMM: h1_pre = Wf1a * xi, K=128
#pragma unroll 1
        for (int c = 0; c < 4; c++)
            consume(sb, cc, pc, 0u, 17408u, ST_E, c * 2, acc, c == 0, wm, wn, lane, tid);

        // f2: qv = bf2 + sum_c lrelu(h1_pre + p + bf1) * wf2
        {
            const float* psrc = (const float*)(g_pscr + ((size_t)tile * 8 + a) * 32768);
            float part[4];
#pragma unroll
            for (int i = 0; i < 4; i++) part[i] = 0.f;
            const float* b1a = bf1 + a * 128;
            const float* w2a = wf2 + a * 128;
#pragma unroll
            for (int im = 0; im < 2; im++)
#pragma unroll
                for (int in = 0; in < 4; in++) {
                    int c = wn * 32 + in * 8 + t4 * 2;
                    int r0 = wm * 32 + im * 16 + g;
                    float2 pa = __ldg((const float2*)(psrc + (size_t)r0 * 128 + c));
                    float2 pb = __ldg((const float2*)(psrc + (size_t)(r0 + 8) * 128 + c));
                    float b0 = __ldg(b1a + c), b1 = __ldg(b1a + c + 1);
                    float w0 = __ldg(w2a + c), w1 = __ldg(w2a + c + 1);
                    part[im * 2 + 0] += lrelu(acc[im][in][0] + pa.x + b0) * w0
                                      + lrelu(acc[im][in][1] + pa.y + b1) * w1;
                    part[im * 2 + 1] += lrelu(acc[im][in][2] + pb.x + b0) * w0
                                      + lrelu(acc[im][in][3] + pb.y + b1) * w1;
                }
#pragma unroll
            for (int i = 0; i < 4; i++) {
                part[i] += __shfl_xor_sync(0xffffffffu, part[i], 1);
                part[i] += __shfl_xor_sync(0xffffffffu, part[i], 2);
            }
            if (t4 == 0) {
#pragma unroll
                for (int i = 0; i < 4; i++) {
                    int row = wm * 32 + (i >> 1) * 16 + g + (i & 1) * 8;
                    ((float*)(sm + F2_OFF))[row * 4 + wn] = part[i];
                }
            }
            __syncthreads();
            if (tid < 64) {
                const float* bp = (const float*)(sm + F2_OFF) + tid * 4;
                float qv = __ldg(bf2 + a) + bp[0] + bp[1] + bp[2] + bp[3];
                out[(size_t)a * 65536 + (size_t)tile * 64 + tid] = qv;
            }
            __syncthreads();
        }
    }
}

// ------------------------------------------------------------------ launcher
extern "C" void kernel_launch(void* const* d_in, const int* in_sizes, int n_in,
                              void* d_out, int out_size) {
    const float* obs = (const float*)d_in[0];
    const float* act = (const float*)d_in[1];
    const float* Wg  = (const float*)d_in[2];
    const float* bg  = (const float*)d_in[3];
    // d_in[4]=Wq, d_in[5]=Wk: dead (softmax over size-1 axis == 1)
    const float* Wv  = (const float*)d_in[6];
    const float* bv  = (const float*)d_in[7];
    const float* Wf1 = (const float*)d_in[8];
    const float* bf1 = (const float*)d_in[9];
    const float* Wf2 = (const float*)d_in[10];
    const float* bf2 = (const float*)d_in[11];
    float* out = (float*)d_out;

    cudaFuncSetAttribute(critic_main, cudaFuncAttributeMaxDynamicSharedMemorySize,
                         SMEM_TOTAL);
    prep_kernel<<<(NPREP + 255) / 256, 256>>>(Wg, Wv, Wf1);
    critic_main<<<1024, 256, SMEM_TOTAL>>>(obs, act, bg, bv, bf1, Wf2, bf2, out);
}

// round 10
// speedup vs baseline: 1.7467x; 1.3177x over previous
#include <cuda_runtime.h>
#include <cuda_fp16.h>
#include <cstdint>
#include <cstddef>

// smem layout (bytes, base-relative), Bt = 64 batch rows per CTA
//  A region: 0 .. 21504   x (ST_X, fp16 hi only) / e,xi (ST_E, fp16 hi only)
//  F2 buf:   17920 .. 18944  (pass 2 only; xi image ends at 17408)
//  CB0/1/2:  22528 / 43008 / 63488, each 20480 (weight chunk: hi 10240 | lo 10240)
#define F2_OFF  17920u
#define CB0_OFF 22528u
#define SMEM_TOTAL 83968
#define ST_X 336      // x row stride bytes (168 fp16; 160 data)
#define ST_E 272      // e/xi row stride bytes (136 fp16)
#define ST_W 80       // weight chunk row stride bytes (40 fp16; 32 data)
#define CHUNK_B 20480 // hi 10240 | lo 10240 (128 rows x 32 kcols)
#define NCHUNKS 136   // pass1: 8*(5 wg + 4 wv + 4 f1b) = 104 ; pass2: 8*4 f1a = 32

// ---------------------------------------------------------------- helpers
__device__ __forceinline__ uint32_t smem_to_u32(const void* p) {
    uint32_t a;
    asm("{ .reg .u64 t; cvta.to.shared.u64 t, %1; cvt.u32.u64 %0, t; }"
        : "=r"(a) : "l"(p));
    return a;
}
__device__ __forceinline__ float lrelu(float x) { return x > 0.f ? x : 0.01f * x; }
__device__ __forceinline__ uint32_t pkh(float a, float b) {
    __half2 t = __floats2half2_rn(a, b);
    return *reinterpret_cast<uint32_t*>(&t);
}

#define LDSM4(r, a) \
    asm volatile("ldmatrix.sync.aligned.m8n8.x4.shared.b16 {%0,%1,%2,%3}, [%4];" \
        : "=r"((r)[0]), "=r"((r)[1]), "=r"((r)[2]), "=r"((r)[3]) : "r"(a))

#define MMA(c, av, b0, b1) \
    asm volatile("mma.sync.aligned.m16n8k16.row.col.f32.f16.f16.f32 " \
        "{%0,%1,%2,%3},{%4,%5,%6,%7},{%8,%9},{%0,%1,%2,%3};" \
        : "+f"((c)[0]), "+f"((c)[1]), "+f"((c)[2]), "+f"((c)[3]) \
        : "r"((av)[0]), "r"((av)[1]), "r"((av)[2]), "r"((av)[3]), "r"(b0), "r"(b1))

#define CPWAIT1() asm volatile("cp.async.wait_group 1;" ::: "memory")
#define CPWAIT0() asm volatile("cp.async.wait_group 0;" ::: "memory")
#define CPCOMMIT() asm volatile("cp.async.commit_group;" ::: "memory")

// ------------------------------------------------------------------- scratch
__device__ __align__(16) char g_wg[8 * 102400];     // per agent: 5 chunks
__device__ __align__(16) char g_wv[81920];          // 4 chunks
__device__ __align__(16) char g_wf1[8 * 163840];    // per agent: f1a c0..3 | f1b c4..7
__device__ __align__(16) char g_vscr[268435456];    // 1024 tiles x 8 agents x 32768 fp32 v
__device__ __align__(16) char g_pscr[268435456];    // 1024 tiles x 8 agents x 32768 fp32 p=Wf1b*e

// --------------------------------------------------------------- prep kernel
#define NWG (8 * 160 * 128)
#define NWV (128 * 128)
#define NWF (8 * 256 * 128)
#define NPREP (NWG + NWV + NWF)

__global__ void prep_kernel(const float* __restrict__ Wg,
                            const float* __restrict__ Wv,
                            const float* __restrict__ Wf1) {
    int i = blockIdx.x * blockDim.x + threadIdx.x;
    if (i >= NPREP) return;
    float v; char* base; int n, k;
    if (i < NWG) {
        int a = i / 20480, r = i - a * 20480;
        k = r >> 7; n = r & 127;
        v = Wg[(size_t)a * 20480 + (size_t)k * 128 + n];
        base = g_wg + (size_t)a * 102400 + (size_t)(k >> 5) * CHUNK_B;
    } else if (i < NWG + NWV) {
        int t = i - NWG;
        k = t >> 7; n = t & 127;
        v = Wv[(size_t)(n >> 5) * 4096 + (size_t)k * 32 + (n & 31)];
        base = g_wv + (size_t)(k >> 5) * CHUNK_B;
    } else {
        int t = i - NWG - NWV;
        int a = t >> 15, r = t & 32767;
        int ii = r >> 7; n = r & 127;
        int p = ii >> 7; k = ii & 127;
        v = Wf1[(size_t)a * 32768 + (size_t)ii * 128 + n];
        base = g_wf1 + (size_t)a * 163840 + (size_t)(p * 4 + (k >> 5)) * CHUNK_B;
    }
    int kk = k & 31;
    __half h = __float2half_rn(v);
    __half l = __float2half_rn(v - __half2float(h));
    *(__half*)(base + (size_t)n * ST_W + kk * 2) = h;
    *(__half*)(base + 10240 + (size_t)n * ST_W + kk * 2) = l;
}

// ---------------------------------------------------------- chunk pipeline
__device__ __forceinline__ const char* chunk_src(int i) {
    if (i < 104) {
        int a = i / 13, c = i - a * 13;
        if (c < 5) return g_wg + (size_t)a * 102400 + (size_t)c * CHUNK_B;
        if (c < 9) return g_wv + (size_t)(c - 5) * CHUNK_B;
        return g_wf1 + (size_t)a * 163840 + (size_t)(c - 5) * CHUNK_B;  // f1b chunks 4..7
    }
    int j = i - 104;
    int a = j >> 2, c = j & 3;
    return g_wf1 + (size_t)a * 163840 + (size_t)c * CHUNK_B;            // f1a chunks 0..3
}

__device__ __forceinline__ void prefetch_chunk(uint32_t sb, int idx, int tid) {
    const char* s = chunk_src(idx) + (size_t)tid * 16;
    uint32_t d = sb + CB0_OFF + (uint32_t)(idx % 3) * 20480u + (uint32_t)tid * 16u;
#pragma unroll
    for (int i = 0; i < 5; i++) {
        asm volatile("cp.async.cg.shared.global [%0], [%1], 16;"
                     :: "r"(d + (uint32_t)i * 4096u), "l"(s + (size_t)i * 4096)
                     : "memory");
    }
    CPCOMMIT();
}

// ------------------------------------------------- warp-tile 32x32 GEMM
// fp16 2-product: a_hi*b_hi + a_hi*b_lo  (A stored hi-only)
__device__ __forceinline__ void gemm_chunk(uint32_t sb, uint32_t aOff, int aStr,
        uint32_t bOff, int kbase, float (&acc)[2][4][4], bool init,
        int wm, int wn, int lane) {
    if (init)
#pragma unroll
        for (int im = 0; im < 2; im++)
#pragma unroll
            for (int in = 0; in < 4; in++)
#pragma unroll
                for (int e = 0; e < 4; e++) acc[im][in][e] = 0.f;
    uint32_t aRow = (uint32_t)(wm * 32 + (lane & 15));
    uint32_t bRow = (uint32_t)(wn * 32 + (lane & 15));
    uint32_t colo = (uint32_t)((lane >> 4) * 16);
#pragma unroll
    for (int ks = 0; ks < 2; ks++) {
        uint32_t coA = (uint32_t)(kbase + ks) * 32 + colo;
        uint32_t coB = (uint32_t)ks * 32 + colo;
        uint32_t ah[2][4], bh[2][4], bl[2][4];
#pragma unroll
        for (int im = 0; im < 2; im++) {
            uint32_t r = (aRow + im * 16) * (uint32_t)aStr + coA;
            LDSM4(ah[im], sb + aOff + r);
        }
#pragma unroll
        for (int ip = 0; ip < 2; ip++) {
            uint32_t r = (bRow + ip * 16) * (uint32_t)ST_W + coB;
            LDSM4(bh[ip], sb + bOff + r);
            LDSM4(bl[ip], sb + bOff + 10240u + r);
        }
#pragma unroll
        for (int im = 0; im < 2; im++)
#pragma unroll
            for (int in = 0; in < 4; in++) {
                uint32_t b0h = bh[in >> 1][in & 1], b1h = bh[in >> 1][(in & 1) + 2];
                uint32_t b0l = bl[in >> 1][in & 1], b1l = bl[in >> 1][(in & 1) + 2];
                MMA(acc[im][in], ah[im], b0h, b1h);
                MMA(acc[im][in], ah[im], b0l, b1l);
            }
    }
}

// triple-buffered: ONE sync per chunk. The sync here guarantees all warps
// finished gemm(cc-1), so prefetch into slot (cc+2)%3 == (cc-1)%3 is safe.
__device__ __forceinline__ void consume(uint32_t sb, int& cc, int& pc,
        uint32_t aOff, int aStr, int kbase, float (&acc)[2][4][4],
        bool init, int wm, int wn, int lane, int tid) {
    if (pc - cc >= 2) CPWAIT1(); else CPWAIT0();
    __syncthreads();
    uint32_t bOff = CB0_OFF + (uint32_t)(cc % 3) * 20480u;
    gemm_chunk(sb, aOff, aStr, bOff, kbase, acc, init, wm, wn, lane);
    if (pc < NCHUNKS) { prefetch_chunk(sb, pc, tid); pc++; }
    cc++;
}

// ----------------------------------------------------------------- main
__global__ __launch_bounds__(256, 2)
void critic_main(const float* __restrict__ obs, const float* __restrict__ act,
                 const float* __restrict__ bg, const float* __restrict__ bvv,
                 const float* __restrict__ bf1, const float* __restrict__ wf2,
                 const float* __restrict__ bf2, float* __restrict__ out) {
    extern __shared__ __align__(16) char sm[];
    uint32_t sb = smem_to_u32(sm);
    int tid = threadIdx.x;
    int lane = tid & 31, wid = tid >> 5;
    int wm = wid & 1, wn = wid >> 1;
    int g = lane >> 2, t4 = lane & 3;
    int tile = blockIdx.x;

    float acc[2][4][4];
    float S[2][4][4];

    // per-thread output column pair (agent-independent); cache bv
    float bv0[4], bv1[4];
#pragma unroll
    for (int in = 0; in < 4; in++) {
        int c = wn * 32 + in * 8 + t4 * 2;
        bv0[in] = __ldg(bvv + c);
        bv1[in] = __ldg(bvv + c + 1);
    }

    int cc = 0, pc = 0;
    prefetch_chunk(sb, pc, tid); pc++;
    prefetch_chunk(sb, pc, tid); pc++;

    // ============================ PASS 1 ============================
    for (int a = 0; a < 8; a++) {
        __syncthreads();   // protect A-region rewrite vs previous phase's reads
        // x rows -> A region (fp16 hi only). 4 threads per row.
        {
            int row = tid >> 2, q = tid & 3;
            size_t rb = (size_t)a * 65536 + (size_t)tile * 64 + row;
            const float4* op = (const float4*)(obs + rb * 128) + q * 8;
            const float4* ap = (const float4*)(act + rb * 32) + q * 2;
            char* hb = sm + (size_t)row * ST_X;
#pragma unroll 4
            for (int i = 0; i < 8; i++) {
                float4 f = __ldg(op + i);
                int k = q * 32 + i * 4;
                *(uint2*)(hb + k * 2) = make_uint2(pkh(f.x, f.y), pkh(f.z, f.w));
            }
#pragma unroll
            for (int i = 0; i < 2; i++) {
                float4 f = __ldg(ap + i);
                int k = 128 + q * 8 + i * 4;
                *(uint2*)(hb + k * 2) = make_uint2(pkh(f.x, f.y), pkh(f.z, f.w));
            }
        }
        // g GEMM: K=160 = 5 chunks
#pragma unroll 1
        for (int c = 0; c < 5; c++)
            consume(sb, cc, pc, 0u, ST_X, c * 2, acc, c == 0, wm, wn, lane, tid);

        __syncthreads();   // all warps done reading x before e overwrites A
        // e = lrelu(acc + bg) -> A region (ST_E fp16 image)
        {
            const float* bga = bg + a * 128;
#pragma unroll
            for (int im = 0; im < 2; im++)
#pragma unroll
                for (int in = 0; in < 4; in++) {
                    int c = wn * 32 + in * 8 + t4 * 2;
                    int r0 = wm * 32 + im * 16 + g;
                    float b0 = __ldg(bga + c), b1 = __ldg(bga + c + 1);
                    *(uint32_t*)(sm + (size_t)r0 * ST_E + c * 2) =
                        pkh(lrelu(acc[im][in][0] + b0), lrelu(acc[im][in][1] + b1));
                    *(uint32_t*)(sm + (size_t)(r0 + 8) * ST_E + c * 2) =
                        pkh(lrelu(acc[im][in][2] + b0), lrelu(acc[im][in][3] + b1));
                }
        }
        // v GEMM: K=128 = 4 chunks (A = e)
#pragma unroll 1
        for (int c = 0; c < 4; c++)
            consume(sb, cc, pc, 0u, ST_E, c * 2, acc, c == 0, wm, wn, lane, tid);
        // v = lrelu(acc + bv): accumulate S in regs, store v to scratch (gmem only)
        {
            float* vdst = (float*)(g_vscr + ((size_t)tile * 8 + a) * 32768);
#pragma unroll
            for (int im = 0; im < 2; im++)
#pragma unroll
                for (int in = 0; in < 4; in++) {
                    int c = wn * 32 + in * 8 + t4 * 2;
                    int r0 = wm * 32 + im * 16 + g;
                    float v0 = lrelu(acc[im][in][0] + bv0[in]);
                    float v1 = lrelu(acc[im][in][1] + bv1[in]);
                    float v2 = lrelu(acc[im][in][2] + bv0[in]);
                    float v3 = lrelu(acc[im][in][3] + bv1[in]);
                    if (a == 0) {
                        S[im][in][0] = v0; S[im][in][1] = v1;
                        S[im][in][2] = v2; S[im][in][3] = v3;
                    } else {
                        S[im][in][0] += v0; S[im][in][1] += v1;
                        S[im][in][2] += v2; S[im][in][3] += v3;
                    }
                    *(float2*)(vdst + (size_t)r0 * 128 + c) = make_float2(v0, v1);
                    *(float2*)(vdst + (size_t)(r0 + 8) * 128 + c) = make_float2(v2, v3);
                }
        }
        // p GEMM: p = Wf1b * e, K=128 (A = e, still resident)
#pragma unroll 1
        for (int c = 0; c < 4; c++)
            consume(sb, cc, pc, 0u, ST_E, c * 2, acc, c == 0, wm, wn, lane, tid);
        // p -> scratch (raw fp32, gmem only)
        {
            float* pdst = (float*)(g_pscr + ((size_t)tile * 8 + a) * 32768);
#pragma unroll
            for (int im = 0; im < 2; im++)
#pragma unroll
                for (int in = 0; in < 4; in++) {
                    int c = wn * 32 + in * 8 + t4 * 2;
                    int r0 = wm * 32 + im * 16 + g;
                    *(float2*)(pdst + (size_t)r0 * 128 + c) =
                        make_float2(acc[im][in][0], acc[im][in][1]);
                    *(float2*)(pdst + (size_t)(r0 + 8) * 128 + c) =
                        make_float2(acc[im][in][2], acc[im][in][3]);
                }
        }
    }

    // ============================ PASS 2 ============================
    for (int a = 0; a < 8; a++) {
        __syncthreads();   // all warps done with previous f1a reads of A
        // xi = S - v -> A region (ST_E fp16 image)
        {
            const float* vsrc = (const float*)(g_vscr + ((size_t)tile * 8 + a) * 32768);
#pragma unroll
            for (int im = 0; im < 2; im++)
#pragma unroll
                for (int in = 0; in < 4; in++) {
                    int c = wn * 32 + in * 8 + t4 * 2;
                    int r0 = wm * 32 + im * 16 + g;
                    float2 va = __ldg((const float2*)(vsrc + (size_t)r0 * 128 + c));
                    float2 vb = __ldg((const float2*)(vsrc + (size_t)(r0 + 8) * 128 + c));
                    *(uint32_t*)(sm + (size_t)r0 * ST_E + c * 2) =
                        pkh(S[im][in][0] - va.x, S[im][in][1] - va.y);
                    *(uint32_t*)(sm + (size_t)(r0 + 8) * ST_E + c * 2) =
                        pkh(S[im][in][2] - vb.x, S[im][in][3] - vb.y);
                }
        }
        // f1a GEMM: h1_pre = Wf1a * xi, K=128
#pragma unroll 1
        for (int c = 0; c < 4; c++)
            consume(sb, cc, pc, 0u, ST_E, c * 2, acc, c == 0, wm, wn, lane, tid);

        // f2: qv = bf2 + sum_c lrelu(h1_pre + p + bf1) * wf2
        {
            const float* psrc = (const float*)(g_pscr + ((size_t)tile * 8 + a) * 32768);
            float part[4];
#pragma unroll
            for (int i = 0; i < 4; i++) part[i] = 0.f;
            const float* b1a = bf1 + a * 128;
            const float* w2a = wf2 + a * 128;
#pragma unroll
            for (int im = 0; im < 2; im++)
#pragma unroll
                for (int in = 0; in < 4; in++) {
                    int c = wn * 32 + in * 8 + t4 * 2;
                    int r0 = wm * 32 + im * 16 + g;
                    float2 pa = __ldg((const float2*)(psrc + (size_t)r0 * 128 + c));
                    float2 pb = __ldg((const float2*)(psrc + (size_t)(r0 + 8) * 128 + c));
                    float b0 = __ldg(b1a + c), b1 = __ldg(b1a + c + 1);
                    float w0 = __ldg(w2a + c), w1 = __ldg(w2a + c + 1);
                    part[im * 2 + 0] += lrelu(acc[im][in][0] + pa.x + b0) * w0
                                      + lrelu(acc[im][in][1] + pa.y + b1) * w1;
                    part[im * 2 + 1] += lrelu(acc[im][in][2] + pb.x + b0) * w0
                                      + lrelu(acc[im][in][3] + pb.y + b1) * w1;
                }
#pragma unroll
            for (int i = 0; i < 4; i++) {
                part[i] += __shfl_xor_sync(0xffffffffu, part[i], 1);
                part[i] += __shfl_xor_sync(0xffffffffu, part[i], 2);
            }
            if (t4 == 0) {
#pragma unroll
                for (int i = 0; i < 4; i++) {
                    int row = wm * 32 + (i >> 1) * 16 + g + (i & 1) * 8;
                    ((float*)(sm + F2_OFF))[row * 4 + wn] = part[i];
                }
            }
            __syncthreads();
            if (tid < 64) {
                const float* bp = (const float*)(sm + F2_OFF) + tid * 4;
                float qv = __ldg(bf2 + a) + bp[0] + bp[1] + bp[2] + bp[3];
                out[(size_t)a * 65536 + (size_t)tile * 64 + tid] = qv;
            }
        }
    }
}

// ------------------------------------------------------------------ launcher
extern "C" void kernel_launch(void* const* d_in, const int* in_sizes, int n_in,
                              void* d_out, int out_size) {
    const float* obs = (const float*)d_in[0];
    const float* act = (const float*)d_in[1];
    const float* Wg  = (const float*)d_in[2];
    const float* bg  = (const float*)d_in[3];
    // d_in[4]=Wq, d_in[5]=Wk: dead (softmax over size-1 axis == 1)
    const float* Wv  = (const float*)d_in[6];
    const float* bv  = (const float*)d_in[7];
    const float* Wf1 = (const float*)d_in[8];
    const float* bf1 = (const float*)d_in[9];
    const float* Wf2 = (const float*)d_in[10];
    const float* bf2 = (const float*)d_in[11];
    float* out = (float*)d_out;

    cudaFuncSetAttribute(critic_main, cudaFuncAttributeMaxDynamicSharedMemorySize,
                         SMEM_TOTAL);
    prep_kernel<<<(NPREP + 255) / 256, 256>>>(Wg, Wv, Wf1);
    critic_main<<<1024, 256, SMEM_TOTAL>>>(obs, act, bg, bv, bf1, Wf2, bf2, out);
}

// round 12
// speedup vs baseline: 2.1713x; 1.2430x over previous
#include <cuda_runtime.h>
#include <cuda_fp16.h>
#include <cstdint>
#include <cstddef>

// smem layout (bytes, base-relative), Bt = 64 batch rows per CTA
//  A region: 0 .. 21504   x (ST_X, fp16) / e,xi (ST_E, fp16)
//  F2 buf:   17920 .. 18944  (pass 2 only; xi image ends at 17408)
//  CB0/1/2:  22528 + {0,1,2}*10240  (weight chunk, fp16, 128 rows x 32 kcols)
#define F2_OFF  17920u
#define CB0_OFF 22528u
#define SMEM_TOTAL 53248
#define ST_X 336      // x row stride bytes (168 fp16; 160 data)
#define ST_E 272      // e/xi row stride bytes (136 fp16)
#define ST_W 80       // weight chunk row stride bytes (40 fp16; 32 data)
#define CHUNK_B 10240 // 128 rows x 80 B
#define NCHUNKS 136   // pass1: 8*(5 wg + 4 wv + 4 f1b) = 104 ; pass2: 8*4 f1a = 32

// ---------------------------------------------------------------- helpers
__device__ __forceinline__ uint32_t smem_to_u32(const void* p) {
    uint32_t a;
    asm("{ .reg .u64 t; cvta.to.shared.u64 t, %1; cvt.u32.u64 %0, t; }"
        : "=r"(a) : "l"(p));
    return a;
}
__device__ __forceinline__ float lrelu(float x) { return x > 0.f ? x : 0.01f * x; }
__device__ __forceinline__ uint32_t pkh(float a, float b) {
    __half2 t = __floats2half2_rn(a, b);
    return *reinterpret_cast<uint32_t*>(&t);
}

#define LDSM4(r, a) \
    asm volatile("ldmatrix.sync.aligned.m8n8.x4.shared.b16 {%0,%1,%2,%3}, [%4];" \
        : "=r"((r)[0]), "=r"((r)[1]), "=r"((r)[2]), "=r"((r)[3]) : "r"(a))

#define MMA(c, av, b0, b1) \
    asm volatile("mma.sync.aligned.m16n8k16.row.col.f32.f16.f16.f32 " \
        "{%0,%1,%2,%3},{%4,%5,%6,%7},{%8,%9},{%0,%1,%2,%3};" \
        : "+f"((c)[0]), "+f"((c)[1]), "+f"((c)[2]), "+f"((c)[3]) \
        : "r"((av)[0]), "r"((av)[1]), "r"((av)[2]), "r"((av)[3]), "r"(b0), "r"(b1))

#define CPWAIT1() asm volatile("cp.async.wait_group 1;" ::: "memory")
#define CPWAIT0() asm volatile("cp.async.wait_group 0;" ::: "memory")
#define CPCOMMIT() asm volatile("cp.async.commit_group;" ::: "memory")

// ------------------------------------------------------------------- scratch
__device__ __align__(16) char g_wg[8 * 51200];      // per agent: 5 chunks
__device__ __align__(16) char g_wv[40960];          // 4 chunks
__device__ __align__(16) char g_wf1[8 * 81920];     // per agent: f1a c0..3 | f1b c4..7
__device__ __align__(16) char g_vscr[268435456];    // 1024 tiles x 8 agents x 32768 fp32 v
__device__ __align__(16) char g_pscr[268435456];    // 1024 tiles x 8 agents x 32768 fp32 p=Wf1b*e

// --------------------------------------------------------------- prep kernel
#define NWG (8 * 160 * 128)
#define NWV (128 * 128)
#define NWF (8 * 256 * 128)
#define NPREP (NWG + NWV + NWF)

__global__ void prep_kernel(const float* __restrict__ Wg,
                            const float* __restrict__ Wv,
                            const float* __restrict__ Wf1) {
    int i = blockIdx.x * blockDim.x + threadIdx.x;
    if (i >= NPREP) return;
    float v; char* base; int n, k;
    if (i < NWG) {
        int a = i / 20480, r = i - a * 20480;
        k = r >> 7; n = r & 127;
        v = Wg[(size_t)a * 20480 + (size_t)k * 128 + n];
        base = g_wg + (size_t)a * 51200 + (size_t)(k >> 5) * CHUNK_B;
    } else if (i < NWG + NWV) {
        int t = i - NWG;
        k = t >> 7; n = t & 127;
        v = Wv[(size_t)(n >> 5) * 4096 + (size_t)k * 32 + (n & 31)];
        base = g_wv + (size_t)(k >> 5) * CHUNK_B;
    } else {
        int t = i - NWG - NWV;
        int a = t >> 15, r = t & 32767;
        int ii = r >> 7; n = r & 127;
        int p = ii >> 7; k = ii & 127;
        v = Wf1[(size_t)a * 32768 + (size_t)ii * 128 + n];
        base = g_wf1 + (size_t)a * 81920 + (size_t)(p * 4 + (k >> 5)) * CHUNK_B;
    }
    int kk = k & 31;
    *(__half*)(base + (size_t)n * ST_W + kk * 2) = __float2half_rn(v);
}

// ---------------------------------------------------------- chunk pipeline
__device__ __forceinline__ const char* chunk_src(int i) {
    if (i < 104) {
        int a = i / 13, c = i - a * 13;
        if (c < 5) return g_wg + (size_t)a * 51200 + (size_t)c * CHUNK_B;
        if (c < 9) return g_wv + (size_t)(c - 5) * CHUNK_B;
        return g_wf1 + (size_t)a * 81920 + (size_t)(c - 5) * CHUNK_B;  // f1b chunks 4..7
    }
    int j = i - 104;
    int a = j >> 2, c = j & 3;
    return g_wf1 + (size_t)a * 81920 + (size_t)c * CHUNK_B;            // f1a chunks 0..3
}

__device__ __forceinline__ void prefetch_chunk(uint32_t sb, int idx, int tid) {
    const char* s = chunk_src(idx) + (size_t)tid * 16;
    uint32_t d = sb + CB0_OFF + (uint32_t)(idx % 3) * (uint32_t)CHUNK_B
               + (uint32_t)tid * 16u;
    // 10240 B = 256 threads * 16 B * 2.5
    asm volatile("cp.async.cg.shared.global [%0], [%1], 16;"
                 :: "r"(d), "l"(s) : "memory");
    asm volatile("cp.async.cg.shared.global [%0], [%1], 16;"
                 :: "r"(d + 4096u), "l"(s + 4096) : "memory");
    if (tid < 128)
        asm volatile("cp.async.cg.shared.global [%0], [%1], 16;"
                     :: "r"(d + 8192u), "l"(s + 8192) : "memory");
    CPCOMMIT();
}

// ------------------------------------------------- warp-tile 32x32 GEMM
// pure fp16 single product
__device__ __forceinline__ void gemm_chunk(uint32_t sb, uint32_t aOff, int aStr,
        uint32_t bOff, int kbase, float (&acc)[2][4][4], bool init,
        int wm, int wn, int lane) {
    if (init)
#pragma unroll
        for (int im = 0; im < 2; im++)
#pragma unroll
            for (int in = 0; in < 4; in++)
#pragma unroll
                for (int e = 0; e < 4; e++) acc[im][in][e] = 0.f;
    uint32_t aRow = (uint32_t)(wm * 32 + (lane & 15));
    uint32_t bRow = (uint32_t)(wn * 32 + (lane & 15));
    uint32_t colo = (uint32_t)((lane >> 4) * 16);
#pragma unroll
    for (int ks = 0; ks < 2; ks++) {
        uint32_t coA = (uint32_t)(kbase + ks) * 32 + colo;
        uint32_t coB = (uint32_t)ks * 32 + colo;
        uint32_t ah[2][4], bh[2][4];
#pragma unroll
        for (int im = 0; im < 2; im++) {
            uint32_t r = (aRow + im * 16) * (uint32_t)aStr + coA;
            LDSM4(ah[im], sb + aOff + r);
        }
#pragma unroll
        for (int ip = 0; ip < 2; ip++) {
            uint32_t r = (bRow + ip * 16) * (uint32_t)ST_W + coB;
            LDSM4(bh[ip], sb + bOff + r);
        }
#pragma unroll
        for (int im = 0; im < 2; im++)
#pragma unroll
            for (int in = 0; in < 4; in++) {
                uint32_t b0h = bh[in >> 1][in & 1], b1h = bh[in >> 1][(in & 1) + 2];
                MMA(acc[im][in], ah[im], b0h, b1h);
            }
    }
}

// triple-buffered: ONE sync per chunk. The sync guarantees all warps finished
// gemm(cc-1), so prefetch into slot (cc+2)%3 == (cc-1)%3 is safe.
__device__ __forceinline__ void consume(uint32_t sb, int& cc, int& pc,
        uint32_t aOff, int aStr, int kbase, float (&acc)[2][4][4],
        bool init, int wm, int wn, int lane, int tid) {
    if (pc - cc >= 2) CPWAIT1(); else CPWAIT0();
    __syncthreads();
    uint32_t bOff = CB0_OFF + (uint32_t)(cc % 3) * (uint32_t)CHUNK_B;
    gemm_chunk(sb, aOff, aStr, bOff, kbase, acc, init, wm, wn, lane);
    if (pc < NCHUNKS) { prefetch_chunk(sb, pc, tid); pc++; }
    cc++;
}

// ----------------------------------------------------------------- main
__global__ __launch_bounds__(256, 2)
void critic_main(const float* __restrict__ obs, const float* __restrict__ act,
                 const float* __restrict__ bg, const float* __restrict__ bvv,
                 const float* __restrict__ bf1, const float* __restrict__ wf2,
                 const float* __restrict__ bf2, float* __restrict__ out) {
    extern __shared__ __align__(16) char sm[];
    uint32_t sb = smem_to_u32(sm);
    int tid = threadIdx.x;
    int lane = tid & 31, wid = tid >> 5;
    int wm = wid & 1, wn = wid >> 1;
    int g = lane >> 2, t4 = lane & 3;
    int tile = blockIdx.x;

    float acc[2][4][4];
    float S[2][4][4];

    // cache bv for this thread's column pair
    float bv0[4], bv1[4];
#pragma unroll
    for (int in = 0; in < 4; in++) {
        int c = wn * 32 + in * 8 + t4 * 2;
        bv0[in] = __ldg(bvv + c);
        bv1[in] = __ldg(bvv + c + 1);
    }

    int cc = 0, pc = 0;
    prefetch_chunk(sb, pc, tid); pc++;
    prefetch_chunk(sb, pc, tid); pc++;

    // ============================ PASS 1 ============================
    for (int a = 0; a < 8; a++) {
        __syncthreads();   // protect A-region rewrite vs previous phase's reads
        // x rows -> A region (fp16). 4 threads per row.
        {
            int row = tid >> 2, q = tid & 3;
            size_t rb = (size_t)a * 65536 + (size_t)tile * 64 + row;
            const float4* op = (const float4*)(obs + rb * 128) + q * 8;
            const float4* ap = (const float4*)(act + rb * 32) + q * 2;
            char* hb = sm + (size_t)row * ST_X;
#pragma unroll 4
            for (int i = 0; i < 8; i++) {
                float4 f = __ldg(op + i);
                int k = q * 32 + i * 4;
                *(uint2*)(hb + k * 2) = make_uint2(pkh(f.x, f.y), pkh(f.z, f.w));
            }
#pragma unroll
            for (int i = 0; i < 2; i++) {
                float4 f = __ldg(ap + i);
                int k = 128 + q * 8 + i * 4;
                *(uint2*)(hb + k * 2) = make_uint2(pkh(f.x, f.y), pkh(f.z, f.w));
            }
        }
        // g GEMM: K=160 = 5 chunks
#pragma unroll 1
        for (int c = 0; c < 5; c++)
            consume(sb, cc, pc, 0u, ST_X, c * 2, acc, c == 0, wm, wn, lane, tid);

        __syncthreads();   // all warps done reading x before e overwrites A
        // e = lrelu(acc + bg) -> A region (ST_E fp16 image)
        {
            const float* bga = bg + a * 128;
#pragma unroll
            for (int im = 0; im < 2; im++)
#pragma unroll
                for (int in = 0; in < 4; in++) {
                    int c = wn * 32 + in * 8 + t4 * 2;
                    int r0 = wm * 32 + im * 16 + g;
                    float b0 = __ldg(bga + c), b1 = __ldg(bga + c + 1);
                    *(uint32_t*)(sm + (size_t)r0 * ST_E + c * 2) =
                        pkh(lrelu(acc[im][in][0] + b0), lrelu(acc[im][in][1] + b1));
                    *(uint32_t*)(sm + (size_t)(r0 + 8) * ST_E + c * 2) =
                        pkh(lrelu(acc[im][in][2] + b0), lrelu(acc[im][in][3] + b1));
                }
        }
        // v GEMM: K=128 = 4 chunks (A = e)
#pragma unroll 1
        for (int c = 0; c < 4; c++)
            consume(sb, cc, pc, 0u, ST_E, c * 2, acc, c == 0, wm, wn, lane, tid);
        // v = lrelu(acc + bv): accumulate S in regs, store v to scratch (gmem only)
        {
            float* vdst = (float*)(g_vscr + ((size_t)tile * 8 + a) * 32768);
#pragma unroll
            for (int im = 0; im < 2; im++)
#pragma unroll
                for (int in = 0; in < 4; in++) {
                    int c = wn * 32 + in * 8 + t4 * 2;
                    int r0 = wm * 32 + im * 16 + g;
                    float v0 = lrelu(acc[im][in][0] + bv0[in]);
                    float v1 = lrelu(acc[im][in][1] + bv1[in]);
                    float v2 = lrelu(acc[im][in][2] + bv0[in]);
                    float v3 = lrelu(acc[im][in][3] + bv1[in]);
                    if (a == 0) {
                        S[im][in][0] = v0; S[im][in][1] = v1;
                        S[im][in][2] = v2; S[im][in][3] = v3;
                    } else {
                        S[im][in][0] += v0; S[im][in][1] += v1;
                        S[im][in][2] += v2; S[im][in][3] += v3;
                    }
                    *(float2*)(vdst + (size_t)r0 * 128 + c) = make_float2(v0, v1);
                    *(float2*)(vdst + (size_t)(r0 + 8) * 128 + c) = make_float2(v2, v3);
                }
        }
        // p GEMM: p = Wf1b * e, K=128 (A = e, still resident)
#pragma unroll 1
        for (int c = 0; c < 4; c++)
            consume(sb, cc, pc, 0u, ST_E, c * 2, acc, c == 0, wm, wn, lane, tid);
        // p -> scratch (raw fp32, gmem only)
        {
            float* pdst = (float*)(g_pscr + ((size_t)tile * 8 + a) * 32768);
#pragma unroll
            for (int im = 0; im < 2; im++)
#pragma unroll
                for (int in = 0; in < 4; in++) {
                    int c = wn * 32 + in * 8 + t4 * 2;
                    int r0 = wm * 32 + im * 16 + g;
                    *(float2*)(pdst + (size_t)r0 * 128 + c) =
                        make_float2(acc[im][in][0], acc[im][in][1]);
                    *(float2*)(pdst + (size_t)(r0 + 8) * 128 + c) =
                        make_float2(acc[im][in][2], acc[im][in][3]);
                }
        }
    }

    // ============================ PASS 2 ============================
    for (int a = 0; a < 8; a++) {
        __syncthreads();   // all warps done with previous f1a reads of A
        // xi = S - v -> A region (ST_E fp16 image)
        {
            const float* vsrc = (const float*)(g_vscr + ((size_t)tile * 8 + a) * 32768);
#pragma unroll
            for (int im = 0; im < 2; im++)
#pragma unroll
                for (int in = 0; in < 4; in++) {
                    int c = wn * 32 + in * 8 + t4 * 2;
                    int r0 = wm * 32 + im * 16 + g;
                    float2 va = __ldg((const float2*)(vsrc + (size_t)r0 * 128 + c));
                    float2 vb = __ldg((const float2*)(vsrc + (size_t)(r0 + 8) * 128 + c));
                    *(uint32_t*)(sm + (size_t)r0 * ST_E + c * 2) =
                        pkh(S[im][in][0] - va.x, S[im][in][1] - va.y);
                    *(uint32_t*)(sm + (size_t)(r0 + 8) * ST_E + c * 2) =
                        pkh(S[im][in][2] - vb.x, S[im][in][3] - vb.y);
                }
        }
        // f1a GEMM: h1_pre = Wf1a * xi, K=128
#pragma unroll 1
        for (int c = 0; c < 4; c++)
            consume(sb, cc, pc, 0u, ST_E, c * 2, acc, c == 0, wm, wn, lane, tid);

        // f2: qv = bf2 + sum_c lrelu(h1_pre + p + bf1) * wf2
        {
            const float* psrc = (const float*)(g_pscr + ((size_t)tile * 8 + a) * 32768);
            float part[4];
#pragma unroll
            for (int i = 0; i < 4; i++) part[i] = 0.f;
            const float* b1a = bf1 + a * 128;
            const float* w2a = wf2 + a * 128;
#pragma unroll
            for (int im = 0; im < 2; im++)
#pragma unroll
                for (int in = 0; in < 4; in++) {
                    int c = wn * 32 + in * 8 + t4 * 2;
                    int r0 = wm * 32 + im * 16 + g;
                    float2 pa = __ldg((const float2*)(psrc + (size_t)r0 * 128 + c));
                    float2 pb = __ldg((const float2*)(psrc + (size_t)(r0 + 8) * 128 + c));
                    float b0 = __ldg(b1a + c), b1 = __ldg(b1a + c + 1);
                    float w0 = __ldg(w2a + c), w1 = __ldg(w2a + c + 1);
                    part[im * 2 + 0] += lrelu(acc[im][in][0] + pa.x + b0) * w0
                                      + lrelu(acc[im][in][1] + pa.y + b1) * w1;
                    part[im * 2 + 1] += lrelu(acc[im][in][2] + pb.x + b0) * w0
                                      + lrelu(acc[im][in][3] + pb.y + b1) * w1;
                }
#pragma unroll
            for (int i = 0; i < 4; i++) {
                part[i] += __shfl_xor_sync(0xffffffffu, part[i], 1);
                part[i] += __shfl_xor_sync(0xffffffffu, part[i], 2);
            }
            if (t4 == 0) {
#pragma unroll
                for (int i = 0; i < 4; i++) {
                    int row = wm * 32 + (i >> 1) * 16 + g + (i & 1) * 8;
                    ((float*)(sm + F2_OFF))[row * 4 + wn] = part[i];
                }
            }
            __syncthreads();
            if (tid < 64) {
                const float* bp = (const float*)(sm + F2_OFF) + tid * 4;
                float qv = __ldg(bf2 + a) + bp[0] + bp[1] + bp[2] + bp[3];
                out[(size_t)a * 65536 + (size_t)tile * 64 + tid] = qv;
            }
        }
    }
}

// ------------------------------------------------------------------ launcher
extern "C" void kernel_launch(void* const* d_in, const int* in_sizes, int n_in,
                              void* d_out, int out_size) {
    const float* obs = (const float*)d_in[0];
    const float* act = (const float*)d_in[1];
    const float* Wg  = (const float*)d_in[2];
    const float* bg  = (const float*)d_in[3];
    // d_in[4]=Wq, d_in[5]=Wk: dead (softmax over size-1 axis == 1)
    const float* Wv  = (const float*)d_in[6];
    const float* bv  = (const float*)d_in[7];
    const float* Wf1 = (const float*)d_in[8];
    const float* bf1 = (const float*)d_in[9];
    const float* Wf2 = (const float*)d_in[10];
    const float* bf2 = (const float*)d_in[11];
    float* out = (float*)d_out;

    cudaFuncSetAttribute(critic_main, cudaFuncAttributeMaxDynamicSharedMemorySize,
                         SMEM_TOTAL);
    prep_kernel<<<(NPREP + 255) / 256, 256>>>(Wg, Wv, Wf1);
    critic_main<<<1024, 256, SMEM_TOTAL>>>(obs, act, bg, bv, bf1, Wf2, bf2, out);
}

// round 13
// speedup vs baseline: 2.3656x; 1.0895x over previous
#include <cuda_runtime.h>
#include <cuda_fp16.h>
#include <cstdint>
#include <cstddef>

// smem layout (bytes, base-relative), Bt = 64 batch rows per CTA
//  A region: 0 .. 21504   x (ST_X, fp16) / e,xi (ST_E, fp16)
//  F2 buf:   17920 .. 18944  (pass 2 only; xi image ends at 17408)
//  CB0/1/2:  22528 + {0,1,2}*20480  (weight chunk slots, fp16, 128 rows x <=64 kcols)
#define F2_OFF  17920u
#define CB0_OFF 22528u
#define SMEM_TOTAL 83968
#define ST_X 336      // x row stride bytes (168 fp16; 160 data)
#define ST_E 272      // e/xi row stride bytes (136 fp16)
#define ST_WF 144     // full weight chunk row stride (72 fp16; 64 data)
#define ST_WH 80      // half weight chunk row stride (40 fp16; 32 data)
#define SLOT_B 20480  // slot size (full chunk 128 x 144 B = 18432 <= slot; we store 20480-packed)
#define NCHUNKS 72    // pass1: 8*(2 wg + 1 wg-half + 2 wv + 2 f1b) = 56 ; pass2: 8*2 f1a = 16

// full chunk bytes = 128*144 = 18432 ; half = 128*80 = 10240
#define FULL_B 18432
#define HALF_B 10240

// ---------------------------------------------------------------- helpers
__device__ __forceinline__ uint32_t smem_to_u32(const void* p) {
    uint32_t a;
    asm("{ .reg .u64 t; cvta.to.shared.u64 t, %1; cvt.u32.u64 %0, t; }"
        : "=r"(a) : "l"(p));
    return a;
}
__device__ __forceinline__ float lrelu(float x) { return x > 0.f ? x : 0.01f * x; }
__device__ __forceinline__ uint32_t pkh(float a, float b) {
    __half2 t = __floats2half2_rn(a, b);
    return *reinterpret_cast<uint32_t*>(&t);
}
__device__ __forceinline__ float2 uph(uint32_t u) {
    __half2 h = *reinterpret_cast<__half2*>(&u);
    return __half22float2(h);
}

#define LDSM4(r, a) \
    asm volatile("ldmatrix.sync.aligned.m8n8.x4.shared.b16 {%0,%1,%2,%3}, [%4];" \
        : "=r"((r)[0]), "=r"((r)[1]), "=r"((r)[2]), "=r"((r)[3]) : "r"(a))

#define MMA(c, av, b0, b1) \
    asm volatile("mma.sync.aligned.m16n8k16.row.col.f32.f16.f16.f32 " \
        "{%0,%1,%2,%3},{%4,%5,%6,%7},{%8,%9},{%0,%1,%2,%3};" \
        : "+f"((c)[0]), "+f"((c)[1]), "+f"((c)[2]), "+f"((c)[3]) \
        : "r"((av)[0]), "r"((av)[1]), "r"((av)[2]), "r"((av)[3]), "r"(b0), "r"(b1))

#define CPWAIT1() asm volatile("cp.async.wait_group 1;" ::: "memory")
#define CPWAIT0() asm volatile("cp.async.wait_group 0;" ::: "memory")
#define CPCOMMIT() asm volatile("cp.async.commit_group;" ::: "memory")

// ------------------------------------------------------------------- scratch
__device__ __align__(16) char g_wg[8 * 47104];      // per agent: full,full,half = 18432*2+10240
__device__ __align__(16) char g_wv[36864];          // 2 full
__device__ __align__(16) char g_wf1[8 * 73728];     // per agent: f1a 2 full | f1b 2 full
__device__ __align__(16) char g_vscr[134217728];    // 1024 tiles x 8 agents x 16384 (fp16 v)
__device__ __align__(16) char g_pscr[268435456];    // 1024 tiles x 8 agents x 32768 (fp32 p)

// --------------------------------------------------------------- prep kernel
#define NWG (8 * 160 * 128)
#define NWV (128 * 128)
#define NWF (8 * 256 * 128)
#define NPREP (NWG + NWV + NWF)

__global__ void prep_kernel(const float* __restrict__ Wg,
                            const float* __restrict__ Wv,
                            const float* __restrict__ Wf1) {
    int i = blockIdx.x * blockDim.x + threadIdx.x;
    if (i >= NPREP) return;
    float v; char* base; int n, k, kk, str;
    if (i < NWG) {
        int a = i / 20480, r = i - a * 20480;
        k = r >> 7; n = r & 127;
        v = Wg[(size_t)a * 20480 + (size_t)k * 128 + n];
        int c = k >> 6;                          // 0,1,2
        base = g_wg + (size_t)a * 47104 + (size_t)c * FULL_B;
        if (c < 2) { kk = k & 63; str = ST_WF; }
        else       { kk = k - 128; str = ST_WH; }
    } else if (i < NWG + NWV) {
        int t = i - NWG;
        k = t >> 7; n = t & 127;
        v = Wv[(size_t)(n >> 5) * 4096 + (size_t)k * 32 + (n & 31)];
        base = g_wv + (size_t)(k >> 6) * FULL_B;
        kk = k & 63; str = ST_WF;
    } else {
        int t = i - NWG - NWV;
        int a = t >> 15, r = t & 32767;
        int ii = r >> 7; n = r & 127;
        int p = ii >> 7; k = ii & 127;
        v = Wf1[(size_t)a * 32768 + (size_t)ii * 128 + n];
        base = g_wf1 + (size_t)a * 73728 + (size_t)(p * 2 + (k >> 6)) * FULL_B;
        kk = k & 63; str = ST_WF;
    }
    *(__half*)(base + (size_t)n * str + kk * 2) = __float2half_rn(v);
}

// ---------------------------------------------------------- chunk pipeline
// pass1 per agent (7): wg0(F) wg1(F) wg2(H) wv0 wv1 f1b0 f1b1 ; pass2 (2): f1a0 f1a1
__device__ __forceinline__ const char* chunk_src(int i, bool& half) {
    if (i < 56) {
        int a = i / 7, c = i - a * 7;
        half = (c == 2);
        if (c < 3) return g_wg + (size_t)a * 47104 + (size_t)c * FULL_B;
        if (c < 5) return g_wv + (size_t)(c - 3) * FULL_B;
        return g_wf1 + (size_t)a * 73728 + (size_t)(c - 3) * FULL_B;  // f1b = slots 2,3
    }
    half = false;
    int j = i - 56;
    int a = j >> 1, c = j & 1;
    return g_wf1 + (size_t)a * 73728 + (size_t)c * FULL_B;            // f1a = slots 0,1
}

__device__ __forceinline__ void prefetch_chunk(uint32_t sb, int idx, int tid) {
    bool half;
    const char* s0 = chunk_src(idx, half);
    const char* s = s0 + (size_t)tid * 16;
    uint32_t d = sb + CB0_OFF + (uint32_t)(idx % 3) * (uint32_t)SLOT_B
               + (uint32_t)tid * 16u;
    if (half) {
        // 10240 B = 256*16*2.5
        asm volatile("cp.async.cg.shared.global [%0], [%1], 16;"
                     :: "r"(d), "l"(s) : "memory");
        asm volatile("cp.async.cg.shared.global [%0], [%1], 16;"
                     :: "r"(d + 4096u), "l"(s + 4096) : "memory");
        if (tid < 128)
            asm volatile("cp.async.cg.shared.global [%0], [%1], 16;"
                         :: "r"(d + 8192u), "l"(s + 8192) : "memory");
    } else {
        // 18432 B = 256*16*4.5
#pragma unroll
        for (int i = 0; i < 4; i++)
            asm volatile("cp.async.cg.shared.global [%0], [%1], 16;"
                         :: "r"(d + (uint32_t)i * 4096u), "l"(s + (size_t)i * 4096)
                         : "memory");
        if (tid < 128)
            asm volatile("cp.async.cg.shared.global [%0], [%1], 16;"
                         :: "r"(d + 16384u), "l"(s + 16384) : "memory");
    }
    CPCOMMIT();
}

// ------------------------------------------------- warp-tile 32x32 GEMM
template<int NKS, int STW>
__device__ __forceinline__ void gemm_chunk(uint32_t sb, uint32_t aOff, int aStr,
        uint32_t bOff, int kbase, float (&acc)[2][4][4], bool init,
        int wm, int wn, int lane) {
    if (init)
#pragma unroll
        for (int im = 0; im < 2; im++)
#pragma unroll
            for (int in = 0; in < 4; in++)
#pragma unroll
                for (int e = 0; e < 4; e++) acc[im][in][e] = 0.f;
    uint32_t aRow = (uint32_t)(wm * 32 + (lane & 15));
    uint32_t bRow = (uint32_t)(wn * 32 + (lane & 15));
    uint32_t colo = (uint32_t)((lane >> 4) * 16);
    uint32_t aBase0 = sb + aOff + aRow * (uint32_t)aStr + (uint32_t)kbase * 32 + colo;
    uint32_t aBase1 = aBase0 + 16u * (uint32_t)aStr;
    uint32_t bBase0 = sb + bOff + bRow * (uint32_t)STW + colo;
    uint32_t bBase1 = bBase0 + 16u * (uint32_t)STW;
#pragma unroll
    for (int ks = 0; ks < NKS; ks++) {
        uint32_t ah[2][4], bh[2][4];
        LDSM4(ah[0], aBase0 + (uint32_t)ks * 32u);
        LDSM4(ah[1], aBase1 + (uint32_t)ks * 32u);
        LDSM4(bh[0], bBase0 + (uint32_t)ks * 32u);
        LDSM4(bh[1], bBase1 + (uint32_t)ks * 32u);
#pragma unroll
        for (int im = 0; im < 2; im++)
#pragma unroll
            for (int in = 0; in < 4; in++) {
                uint32_t b0h = bh[in >> 1][in & 1], b1h = bh[in >> 1][(in & 1) + 2];
                MMA(acc[im][in], ah[im], b0h, b1h);
            }
    }
}

// triple-buffered: ONE sync per chunk. The sync guarantees all warps finished
// gemm(cc-1), so prefetch into slot (cc+2)%3 == (cc-1)%3 is safe.
template<int NKS, int STW>
__device__ __forceinline__ void consume(uint32_t sb, int& cc, int& pc,
        uint32_t aOff, int aStr, int kbase, float (&acc)[2][4][4],
        bool init, int wm, int wn, int lane, int tid) {
    if (pc - cc >= 2) CPWAIT1(); else CPWAIT0();
    __syncthreads();
    uint32_t bOff = CB0_OFF + (uint32_t)(cc % 3) * (uint32_t)SLOT_B;
    gemm_chunk<NKS, STW>(sb, aOff, aStr, bOff, kbase, acc, init, wm, wn, lane);
    if (pc < NCHUNKS) { prefetch_chunk(sb, pc, tid); pc++; }
    cc++;
}

// ----------------------------------------------------------------- main
__global__ __launch_bounds__(256, 2)
void critic_main(const float* __restrict__ obs, const float* __restrict__ act,
                 const float* __restrict__ bg, const float* __restrict__ bvv,
                 const float* __restrict__ bf1, const float* __restrict__ wf2,
                 const float* __restrict__ bf2, float* __restrict__ out) {
    extern __shared__ __align__(16) char sm[];
    uint32_t sb = smem_to_u32(sm);
    int tid = threadIdx.x;
    int lane = tid & 31, wid = tid >> 5;
    int wm = wid & 1, wn = wid >> 1;
    int g = lane >> 2, t4 = lane & 3;
    int tile = blockIdx.x;

    float acc[2][4][4];
    float S[2][4][4];

    // cache bv for this thread's column pair
    float bv0[4], bv1[4];
#pragma unroll
    for (int in = 0; in < 4; in++) {
        int c = wn * 32 + in * 8 + t4 * 2;
        bv0[in] = __ldg(bvv + c);
        bv1[in] = __ldg(bvv + c + 1);
    }

    int cc = 0, pc = 0;
    prefetch_chunk(sb, pc, tid); pc++;
    prefetch_chunk(sb, pc, tid); pc++;

    // ============================ PASS 1 ============================
    for (int a = 0; a < 8; a++) {
        __syncthreads();   // protect A-region rewrite vs previous phase's reads
        // x rows -> A region (fp16). 4 threads per row.
        {
            int row = tid >> 2, q = tid & 3;
            size_t rb = (size_t)a * 65536 + (size_t)tile * 64 + row;
            const float4* op = (const float4*)(obs + rb * 128) + q * 8;
            const float4* ap = (const float4*)(act + rb * 32) + q * 2;
            char* hb = sm + (size_t)row * ST_X;
#pragma unroll 4
            for (int i = 0; i < 8; i++) {
                float4 f = __ldg(op + i);
                int k = q * 32 + i * 4;
                *(uint2*)(hb + k * 2) = make_uint2(pkh(f.x, f.y), pkh(f.z, f.w));
            }
#pragma unroll
            for (int i = 0; i < 2; i++) {
                float4 f = __ldg(ap + i);
                int k = 128 + q * 8 + i * 4;
                *(uint2*)(hb + k * 2) = make_uint2(pkh(f.x, f.y), pkh(f.z, f.w));
            }
        }
        // g GEMM: K=160 = 2 full + 1 half chunk
        consume<4, ST_WF>(sb, cc, pc, 0u, ST_X, 0, acc, true,  wm, wn, lane, tid);
        consume<4, ST_WF>(sb, cc, pc, 0u, ST_X, 4, acc, false, wm, wn, lane, tid);
        consume<2, ST_WH>(sb, cc, pc, 0u, ST_X, 8, acc, false, wm, wn, lane, tid);

        __syncthreads();   // all warps done reading x before e overwrites A
        // e = lrelu(acc + bg) -> A region (ST_E fp16 image)
        {
            const float* bga = bg + a * 128;
#pragma unroll
            for (int im = 0; im < 2; im++)
#pragma unroll
                for (int in = 0; in < 4; in++) {
                    int c = wn * 32 + in * 8 + t4 * 2;
                    int r0 = wm * 32 + im * 16 + g;
                    float b0 = __ldg(bga + c), b1 = __ldg(bga + c + 1);
                    *(uint32_t*)(sm + (size_t)r0 * ST_E + c * 2) =
                        pkh(lrelu(acc[im][in][0] + b0), lrelu(acc[im][in][1] + b1));
                    *(uint32_t*)(sm + (size_t)(r0 + 8) * ST_E + c * 2) =
                        pkh(lrelu(acc[im][in][2] + b0), lrelu(acc[im][in][3] + b1));
                }
        }
        // v GEMM: K=128 = 2 full chunks (A = e)
        consume<4, ST_WF>(sb, cc, pc, 0u, ST_E, 0, acc, true,  wm, wn, lane, tid);
        consume<4, ST_WF>(sb, cc, pc, 0u, ST_E, 4, acc, false, wm, wn, lane, tid);
        // v = lrelu(acc + bv): accumulate S in regs, store v fp16 to scratch
        {
            char* vdst = g_vscr + ((size_t)tile * 8 + a) * 16384;
#pragma unroll
            for (int im = 0; im < 2; im++)
#pragma unroll
                for (int in = 0; in < 4; in++) {
                    int c = wn * 32 + in * 8 + t4 * 2;
                    int r0 = wm * 32 + im * 16 + g;
                    float v0 = lrelu(acc[im][in][0] + bv0[in]);
                    float v1 = lrelu(acc[im][in][1] + bv1[in]);
                    float v2 = lrelu(acc[im][in][2] + bv0[in]);
                    float v3 = lrelu(acc[im][in][3] + bv1[in]);
                    if (a == 0) {
                        S[im][in][0] = v0; S[im][in][1] = v1;
                        S[im][in][2] = v2; S[im][in][3] = v3;
                    } else {
                        S[im][in][0] += v0; S[im][in][1] += v1;
                        S[im][in][2] += v2; S[im][in][3] += v3;
                    }
                    *(uint32_t*)(vdst + ((size_t)r0 * 128 + c) * 2) = pkh(v0, v1);
                    *(uint32_t*)(vdst + ((size_t)(r0 + 8) * 128 + c) * 2) = pkh(v2, v3);
                }
        }
        // p GEMM: p = Wf1b * e, K=128 (A = e, still resident)
        consume<4, ST_WF>(sb, cc, pc, 0u, ST_E, 0, acc, true,  wm, wn, lane, tid);
        consume<4, ST_WF>(sb, cc, pc, 0u, ST_E, 4, acc, false, wm, wn, lane, tid);
        // p -> scratch (raw fp32, gmem only)
        {
            float* pdst = (float*)(g_pscr + ((size_t)tile * 8 + a) * 32768);
#pragma unroll
            for (int im = 0; im < 2; im++)
#pragma unroll
                for (int in = 0; in < 4; in++) {
                    int c = wn * 32 + in * 8 + t4 * 2;
                    int r0 = wm * 32 + im * 16 + g;
                    *(float2*)(pdst + (size_t)r0 * 128 + c) =
                        make_float2(acc[im][in][0], acc[im][in][1]);
                    *(float2*)(pdst + (size_t)(r0 + 8) * 128 + c) =
                        make_float2(acc[im][in][2], acc[im][in][3]);
                }
        }
    }

    // ============================ PASS 2 ============================
    for (int a = 0; a < 8; a++) {
        __syncthreads();   // all warps done with previous f1a reads of A
        // xi = S - v -> A region (ST_E fp16 image)
        {
            const char* vsrc = g_vscr + ((size_t)tile * 8 + a) * 16384;
#pragma unroll
            for (int im = 0; im < 2; im++)
#pragma unroll
                for (int in = 0; in < 4; in++) {
                    int c = wn * 32 + in * 8 + t4 * 2;
                    int r0 = wm * 32 + im * 16 + g;
                    float2 va = uph(__ldg((const uint32_t*)(vsrc + ((size_t)r0 * 128 + c) * 2)));
                    float2 vb = uph(__ldg((const uint32_t*)(vsrc + ((size_t)(r0 + 8) * 128 + c) * 2)));
                    *(uint32_t*)(sm + (size_t)r0 * ST_E + c * 2) =
                        pkh(S[im][in][0] - va.x, S[im][in][1] - va.y);
                    *(uint32_t*)(sm + (size_t)(r0 + 8) * ST_E + c * 2) =
                        pkh(S[im][in][2] - vb.x, S[im][in][3] - vb.y);
                }
        }
        // f1a GEMM: h1_pre = Wf1a * xi, K=128
        consume<4, ST_WF>(sb, cc, pc, 0u, ST_E, 0, acc, true,  wm, wn, lane, tid);
        consume<4, ST_WF>(sb, cc, pc, 0u, ST_E, 4, acc, false, wm, wn, lane, tid);

        // f2: qv = bf2 + sum_c lrelu(h1_pre + p + bf1) * wf2
        {
            const float* psrc = (const float*)(g_pscr + ((size_t)tile * 8 + a) * 32768);
            float part[4];
#pragma unroll
            for (int i = 0; i < 4; i++) part[i] = 0.f;
            const float* b1a = bf1 + a * 128;
            const float* w2a = wf2 + a * 128;
#pragma unroll
            for (int im = 0; im < 2; im++)
#pragma unroll
                for (int in = 0; in < 4; in++) {
                    int c = wn * 32 + in * 8 + t4 * 2;
                    int r0 = wm * 32 + im * 16 + g;
                    float2 pa = __ldg((const float2*)(psrc + (size_t)r0 * 128 + c));
                    float2 pb = __ldg((const float2*)(psrc + (size_t)(r0 + 8) * 128 + c));
                    float b0 = __ldg(b1a + c), b1 = __ldg(b1a + c + 1);
                    float w0 = __ldg(w2a + c), w1 = __ldg(w2a + c + 1);
                    part[im * 2 + 0] += lrelu(acc[im][in][0] + pa.x + b0) * w0
                                      + lrelu(acc[im][in][1] + pa.y + b1) * w1;
                    part[im * 2 + 1] += lrelu(acc[im][in][2] + pb.x + b0) * w0
                                      + lrelu(acc[im][in][3] + pb.y + b1) * w1;
                }
#pragma unroll
            for (int i = 0; i < 4; i++) {
                part[i] += __shfl_xor_sync(0xffffffffu, part[i], 1);
                part[i] += __shfl_xor_sync(0xffffffffu, part[i], 2);
            }
            if (t4 == 0) {
#pragma unroll
                for (int i = 0; i < 4; i++) {
                    int row = wm * 32 + (i >> 1) * 16 + g + (i & 1) * 8;
                    ((float*)(sm + F2_OFF))[row * 4 + wn] = part[i];
                }
            }
            __syncthreads();
            if (tid < 64) {
                const float* bp = (const float*)(sm + F2_OFF) + tid * 4;
                float qv = __ldg(bf2 + a) + bp[0] + bp[1] + bp[2] + bp[3];
                out[(size_t)a * 65536 + (size_t)tile * 64 + tid] = qv;
            }
        }
    }
}

// ------------------------------------------------------------------ launcher
extern "C" void kernel_launch(void* const* d_in, const int* in_sizes, int n_in,
                              void* d_out, int out_size) {
    const float* obs = (const float*)d_in[0];
    const float* act = (const float*)d_in[1];
    const float* Wg  = (const float*)d_in[2];
    const float* bg  = (const float*)d_in[3];
    // d_in[4]=Wq, d_in[5]=Wk: dead (softmax over size-1 axis == 1)
    const float* Wv  = (const float*)d_in[6];
    const float* bv  = (const float*)d_in[7];
    const float* Wf1 = (const float*)d_in[8];
    const float* bf1 = (const float*)d_in[9];
    const float* Wf2 = (const float*)d_in[10];
    const float* bf2 = (const float*)d_in[11];
    float* out = (float*)d_out;

    cudaFuncSetAttribute(critic_main, cudaFuncAttributeMaxDynamicSharedMemorySize,
                         SMEM_TOTAL);
    prep_kernel<<<(NPREP + 255) / 256, 256>>>(Wg, Wv, Wf1);
    critic_main<<<1024, 256, SMEM_TOTAL>>>(obs, act, bg, bv, bf1, Wf2, bf2, out);
}

// round 14
// speedup vs baseline: 2.4195x; 1.0228x over previous
#include <cuda_runtime.h>
#include <cuda_fp16.h>
#include <cstdint>
#include <cstddef>

// smem layout (bytes, base-relative), Bt = 64 batch rows per CTA
//  X region: 0 .. 21504       x image (ST_X, fp16); F2 partial buffer in pass 2
//  E region: 21504 .. 38912   e (pass1) / xi (pass2) image (ST_E, fp16)
//  CB0/1/2:  38912 + {0,1,2}*18432  weight chunk slots (fp16, 128 rows x <=64 kcols)
#define E_OFF   21504u
#define CB0_OFF 38912u
#define SMEM_TOTAL 94208
#define ST_X 336      // x row stride bytes (168 fp16; 160 data)
#define ST_E 272      // e/xi row stride bytes (136 fp16)
#define ST_WF 144     // full weight chunk row stride (72 fp16; 64 data)
#define ST_WH 80      // half weight chunk row stride (40 fp16; 32 data)
#define NCHUNKS 72    // pass1: 8*(2 wg + 1 wg-half + 2 wv + 2 f1b) = 56 ; pass2: 8*2 f1a = 16
#define FULL_B 18432  // 128 * 144
#define HALF_B 10240  // 128 * 80

// ---------------------------------------------------------------- helpers
__device__ __forceinline__ uint32_t smem_to_u32(const void* p) {
    uint32_t a;
    asm("{ .reg .u64 t; cvta.to.shared.u64 t, %1; cvt.u32.u64 %0, t; }"
        : "=r"(a) : "l"(p));
    return a;
}
__device__ __forceinline__ float lrelu(float x) { return x > 0.f ? x : 0.01f * x; }
__device__ __forceinline__ uint32_t pkh(float a, float b) {
    __half2 t = __floats2half2_rn(a, b);
    return *reinterpret_cast<uint32_t*>(&t);
}
__device__ __forceinline__ float2 uph(uint32_t u) {
    __half2 h = *reinterpret_cast<__half2*>(&u);
    return __half22float2(h);
}

#define LDSM4(r, a) \
    asm volatile("ldmatrix.sync.aligned.m8n8.x4.shared.b16 {%0,%1,%2,%3}, [%4];" \
        : "=r"((r)[0]), "=r"((r)[1]), "=r"((r)[2]), "=r"((r)[3]) : "r"(a))

#define MMA(c, av, b0, b1) \
    asm volatile("mma.sync.aligned.m16n8k16.row.col.f32.f16.f16.f32 " \
        "{%0,%1,%2,%3},{%4,%5,%6,%7},{%8,%9},{%0,%1,%2,%3};" \
        : "+f"((c)[0]), "+f"((c)[1]), "+f"((c)[2]), "+f"((c)[3]) \
        : "r"((av)[0]), "r"((av)[1]), "r"((av)[2]), "r"((av)[3]), "r"(b0), "r"(b1))

#define CPWAIT1() asm volatile("cp.async.wait_group 1;" ::: "memory")
#define CPWAIT0() asm volatile("cp.async.wait_group 0;" ::: "memory")
#define CPCOMMIT() asm volatile("cp.async.commit_group;" ::: "memory")

// ------------------------------------------------------------------- scratch
__device__ __align__(16) char g_wg[8 * 47104];      // per agent: full,full,half
__device__ __align__(16) char g_wv[36864];          // 2 full
__device__ __align__(16) char g_wf1[8 * 73728];     // per agent: f1a 2 full | f1b 2 full
__device__ __align__(16) char g_vscr[134217728];    // 1024 tiles x 8 agents x 16384 (fp16 v)
__device__ __align__(16) char g_pscr[134217728];    // 1024 tiles x 8 agents x 16384 (fp16 p)

// --------------------------------------------------------------- prep kernel
#define NWG (8 * 160 * 128)
#define NWV (128 * 128)
#define NWF (8 * 256 * 128)
#define NPREP (NWG + NWV + NWF)

__global__ void prep_kernel(const float* __restrict__ Wg,
                            const float* __restrict__ Wv,
                            const float* __restrict__ Wf1) {
    int i = blockIdx.x * blockDim.x + threadIdx.x;
    if (i >= NPREP) return;
    float v; char* base; int n, k, kk, str;
    if (i < NWG) {
        int a = i / 20480, r = i - a * 20480;
        k = r >> 7; n = r & 127;
        v = Wg[(size_t)a * 20480 + (size_t)k * 128 + n];
        int c = k >> 6;                          // 0,1,2
        base = g_wg + (size_t)a * 47104 + (size_t)c * FULL_B;
        if (c < 2) { kk = k & 63; str = ST_WF; }
        else       { kk = k - 128; str = ST_WH; }
    } else if (i < NWG + NWV) {
        int t = i - NWG;
        k = t >> 7; n = t & 127;
        v = Wv[(size_t)(n >> 5) * 4096 + (size_t)k * 32 + (n & 31)];
        base = g_wv + (size_t)(k >> 6) * FULL_B;
        kk = k & 63; str = ST_WF;
    } else {
        int t = i - NWG - NWV;
        int a = t >> 15, r = t & 32767;
        int ii = r >> 7; n = r & 127;
        int p = ii >> 7; k = ii & 127;
        v = Wf1[(size_t)a * 32768 + (size_t)ii * 128 + n];
        base = g_wf1 + (size_t)a * 73728 + (size_t)(p * 2 + (k >> 6)) * FULL_B;
        kk = k & 63; str = ST_WF;
    }
    *(__half*)(base + (size_t)n * str + kk * 2) = __float2half_rn(v);
}

// ---------------------------------------------------------- chunk pipeline
// pass1 per agent (7): wg0(F) wg1(F) wg2(H) wv0 wv1 f1b0 f1b1 ; pass2 (2): f1a0 f1a1
__device__ __forceinline__ const char* chunk_src(int i, bool& half) {
    if (i < 56) {
        int a = i / 7, c = i - a * 7;
        half = (c == 2);
        if (c < 3) return g_wg + (size_t)a * 47104 + (size_t)c * FULL_B;
        if (c < 5) return g_wv + (size_t)(c - 3) * FULL_B;
        return g_wf1 + (size_t)a * 73728 + (size_t)(c - 3) * FULL_B;  // f1b = slots 2,3
    }
    half = false;
    int j = i - 56;
    int a = j >> 1, c = j & 1;
    return g_wf1 + (size_t)a * 73728 + (size_t)c * FULL_B;            // f1a = slots 0,1
}

__device__ __forceinline__ void prefetch_chunk(uint32_t sb, int idx, int tid) {
    bool half;
    const char* s0 = chunk_src(idx, half);
    const char* s = s0 + (size_t)tid * 16;
    uint32_t d = sb + CB0_OFF + (uint32_t)(idx % 3) * (uint32_t)FULL_B
               + (uint32_t)tid * 16u;
    if (half) {
        asm volatile("cp.async.cg.shared.global [%0], [%1], 16;"
                     :: "r"(d), "l"(s) : "memory");
        asm volatile("cp.async.cg.shared.global [%0], [%1], 16;"
                     :: "r"(d + 4096u), "l"(s + 4096) : "memory");
        if (tid < 128)
            asm volatile("cp.async.cg.shared.global [%0], [%1], 16;"
                         :: "r"(d + 8192u), "l"(s + 8192) : "memory");
    } else {
#pragma unroll
        for (int i = 0; i < 4; i++)
            asm volatile("cp.async.cg.shared.global [%0], [%1], 16;"
                         :: "r"(d + (uint32_t)i * 4096u), "l"(s + (size_t)i * 4096)
                         : "memory");
        if (tid < 128)
            asm volatile("cp.async.cg.shared.global [%0], [%1], 16;"
                         :: "r"(d + 16384u), "l"(s + 16384) : "memory");
    }
    CPCOMMIT();
}

// ------------------------------------------------- warp-tile 32x32 GEMM
template<int NKS, int STW>
__device__ __forceinline__ void gemm_chunk(uint32_t sb, uint32_t aOff, int aStr,
        uint32_t bOff, int kbase, float (&acc)[2][4][4], bool init,
        int wm, int wn, int lane) {
    if (init)
#pragma unroll
        for (int im = 0; im < 2; im++)
#pragma unroll
            for (int in = 0; in < 4; in++)
#pragma unroll
                for (int e = 0; e < 4; e++) acc[im][in][e] = 0.f;
    uint32_t aRow = (uint32_t)(wm * 32 + (lane & 15));
    uint32_t bRow = (uint32_t)(wn * 32 + (lane & 15));
    uint32_t colo = (uint32_t)((lane >> 4) * 16);
    uint32_t aBase0 = sb + aOff + aRow * (uint32_t)aStr + (uint32_t)kbase * 32 + colo;
    uint32_t aBase1 = aBase0 + 16u * (uint32_t)aStr;
    uint32_t bBase0 = sb + bOff + bRow * (uint32_t)STW + colo;
    uint32_t bBase1 = bBase0 + 16u * (uint32_t)STW;
#pragma unroll
    for (int ks = 0; ks < NKS; ks++) {
        uint32_t ah[2][4], bh[2][4];
        LDSM4(ah[0], aBase0 + (uint32_t)ks * 32u);
        LDSM4(ah[1], aBase1 + (uint32_t)ks * 32u);
        LDSM4(bh[0], bBase0 + (uint32_t)ks * 32u);
        LDSM4(bh[1], bBase1 + (uint32_t)ks * 32u);
#pragma unroll
        for (int im = 0; im < 2; im++)
#pragma unroll
            for (int in = 0; in < 4; in++) {
                uint32_t b0h = bh[in >> 1][in & 1], b1h = bh[in >> 1][(in & 1) + 2];
                MMA(acc[im][in], ah[im], b0h, b1h);
            }
    }
}

// triple-buffered: ONE sync per chunk. The sync guarantees all warps finished
// gemm(cc-1), so prefetch into slot (cc+2)%3 == (cc-1)%3 is safe. It also
// bounds warp drift: a laggard can be inside at most consume(cc) itself,
// which is what makes the epilogues below safe without extra barriers.
template<int NKS, int STW>
__device__ __forceinline__ void consume(uint32_t sb, int& cc, int& pc,
        uint32_t aOff, int aStr, int kbase, float (&acc)[2][4][4],
        bool init, int wm, int wn, int lane, int tid) {
    if (pc - cc >= 2) CPWAIT1(); else CPWAIT0();
    __syncthreads();
    uint32_t bOff = CB0_OFF + (uint32_t)(cc % 3) * (uint32_t)FULL_B;
    gemm_chunk<NKS, STW>(sb, aOff, aStr, bOff, kbase, acc, init, wm, wn, lane);
    if (pc < NCHUNKS) { prefetch_chunk(sb, pc, tid); pc++; }
    cc++;
}

// ----------------------------------------------------------------- main
__global__ __launch_bounds__(256, 2)
void critic_main(const float* __restrict__ obs, const float* __restrict__ act,
                 const float* __restrict__ bg, const float* __restrict__ bvv,
                 const float* __restrict__ bf1, const float* __restrict__ wf2,
                 const float* __restrict__ bf2, float* __restrict__ out) {
    extern __shared__ __align__(16) char sm[];
    uint32_t sb = smem_to_u32(sm);
    int tid = threadIdx.x;
    int lane = tid & 31, wid = tid >> 5;
    int wm = wid & 1, wn = wid >> 1;
    int g = lane >> 2, t4 = lane & 3;
    int tile = blockIdx.x;

    float acc[2][4][4];
    float S[2][4][4];

    // cache bv for this thread's column pair
    float bv0[4], bv1[4];
#pragma unroll
    for (int in = 0; in < 4; in++) {
        int c = wn * 32 + in * 8 + t4 * 2;
        bv0[in] = __ldg(bvv + c);
        bv1[in] = __ldg(bvv + c + 1);
    }

    int cc = 0, pc = 0;
    prefetch_chunk(sb, pc, tid); pc++;
    prefetch_chunk(sb, pc, tid); pc++;

    // ============================ PASS 1 ============================
    // No per-agent barriers: X and E are disjoint regions, and the sync at
    // the top of every consume bounds laggards to the current chunk's gemm,
    // which never reads the region an epilogue writes (audit in comments).
    for (int a = 0; a < 8; a++) {
        // x rows -> X region (fp16). Laggards are in gemm(f1b1 of a-1),
        // which reads E + slot, never X.
        {
            int row = tid >> 2, q = tid & 3;
            size_t rb = (size_t)a * 65536 + (size_t)tile * 64 + row;
            const float4* op = (const float4*)(obs + rb * 128) + q * 8;
            const float4* ap = (const float4*)(act + rb * 32) + q * 2;
            char* hb = sm + (size_t)row * ST_X;
#pragma unroll 4
            for (int i = 0; i < 8; i++) {
                float4 f = __ldg(op + i);
                int k = q * 32 + i * 4;
                *(uint2*)(hb + k * 2) = make_uint2(pkh(f.x, f.y), pkh(f.z, f.w));
            }
#pragma unroll
            for (int i = 0; i < 2; i++) {
                float4 f = __ldg(ap + i);
                int k = 128 + q * 8 + i * 4;
                *(uint2*)(hb + k * 2) = make_uint2(pkh(f.x, f.y), pkh(f.z, f.w));
            }
        }
        // g GEMM: K=160 = 2 full + 1 half chunk (A = X region)
        consume<4, ST_WF>(sb, cc, pc, 0u, ST_X, 0, acc, true,  wm, wn, lane, tid);
        consume<4, ST_WF>(sb, cc, pc, 0u, ST_X, 4, acc, false, wm, wn, lane, tid);
        consume<2, ST_WH>(sb, cc, pc, 0u, ST_X, 8, acc, false, wm, wn, lane, tid);

        // e = lrelu(acc + bg) -> E region. Laggards are in gemm(wg2): read X. Safe.
        {
            const float* bga = bg + a * 128;
#pragma unroll
            for (int im = 0; im < 2; im++)
#pragma unroll
                for (int in = 0; in < 4; in++) {
                    int c = wn * 32 + in * 8 + t4 * 2;
                    int r0 = wm * 32 + im * 16 + g;
                    float b0 = __ldg(bga + c), b1 = __ldg(bga + c + 1);
                    *(uint32_t*)(sm + E_OFF + (size_t)r0 * ST_E + c * 2) =
                        pkh(lrelu(acc[im][in][0] + b0), lrelu(acc[im][in][1] + b1));
                    *(uint32_t*)(sm + E_OFF + (size_t)(r0 + 8) * ST_E + c * 2) =
                        pkh(lrelu(acc[im][in][2] + b0), lrelu(acc[im][in][3] + b1));
                }
        }
        // v GEMM: K=128 = 2 full chunks (A = E region)
        consume<4, ST_WF>(sb, cc, pc, E_OFF, ST_E, 0, acc, true,  wm, wn, lane, tid);
        consume<4, ST_WF>(sb, cc, pc, E_OFF, ST_E, 4, acc, false, wm, wn, lane, tid);
        // v = lrelu(acc + bv): accumulate S in regs, store v fp16 to gmem scratch
        {
            char* vdst = g_vscr + ((size_t)tile * 8 + a) * 16384;
#pragma unroll
            for (int im = 0; im < 2; im++)
#pragma unroll
                for (int in = 0; in < 4; in++) {
                    int c = wn * 32 + in * 8 + t4 * 2;
                    int r0 = wm * 32 + im * 16 + g;
                    float v0 = lrelu(acc[im][in][0] + bv0[in]);
                    float v1 = lrelu(acc[im][in][1] + bv1[in]);
                    float v2 = lrelu(acc[im][in][2] + bv0[in]);
                    float v3 = lrelu(acc[im][in][3] + bv1[in]);
                    if (a == 0) {
                        S[im][in][0] = v0; S[im][in][1] = v1;
                        S[im][in][2] = v2; S[im][in][3] = v3;
                    } else {
                        S[im][in][0] += v0; S[im][in][1] += v1;
                        S[im][in][2] += v2; S[im][in][3] += v3;
                    }
                    *(uint32_t*)(vdst + ((size_t)r0 * 128 + c) * 2) = pkh(v0, v1);
                    *(uint32_t*)(vdst + ((size_t)(r0 + 8) * 128 + c) * 2) = pkh(v2, v3);
                }
        }
        // p GEMM: p = Wf1b * e, K=128 (A = E region, still resident)
        consume<4, ST_WF>(sb, cc, pc, E_OFF, ST_E, 0, acc, true,  wm, wn, lane, tid);
        consume<4, ST_WF>(sb, cc, pc, E_OFF, ST_E, 4, acc, false, wm, wn, lane, tid);
        // p -> gmem scratch (fp16)
        {
            char* pdst = g_pscr + ((size_t)tile * 8 + a) * 16384;
#pragma unroll
            for (int im = 0; im < 2; im++)
#pragma unroll
                for (int in = 0; in < 4; in++) {
                    int c = wn * 32 + in * 8 + t4 * 2;
                    int r0 = wm * 32 + im * 16 + g;
                    *(uint32_t*)(pdst + ((size_t)r0 * 128 + c) * 2) =
                        pkh(acc[im][in][0], acc[im][in][1]);
                    *(uint32_t*)(pdst + ((size_t)(r0 + 8) * 128 + c) * 2) =
                        pkh(acc[im][in][2], acc[im][in][3]);
                }
        }
    }

    // ============================ PASS 2 ============================
    for (int a = 0; a < 8; a++) {
        __syncthreads();   // laggards may read E (xi[a-1]) in gemm(f1a1) and F2 is re-read
        // xi = S - v -> E region (fp16 image)
        {
            const char* vsrc = g_vscr + ((size_t)tile * 8 + a) * 16384;
#pragma unroll
            for (int im = 0; im < 2; im++)
#pragma unroll
                for (int in = 0; in < 4; in++) {
                    int c = wn * 32 + in * 8 + t4 * 2;
                    int r0 = wm * 32 + im * 16 + g;
                    float2 va = uph(__ldg((const uint32_t*)(vsrc + ((size_t)r0 * 128 + c) * 2)));
                    float2 vb = uph(__ldg((const uint32_t*)(vsrc + ((size_t)(r0 + 8) * 128 + c) * 2)));
                    *(uint32_t*)(sm + E_OFF + (size_t)r0 * ST_E + c * 2) =
                        pkh(S[im][in][0] - va.x, S[im][in][1] - va.y);
                    *(uint32_t*)(sm + E_OFF + (size_t)(r0 + 8) * ST_E + c * 2) =
                        pkh(S[im][in][2] - vb.x, S[im][in][3] - vb.y);
                }
        }
        // f1a GEMM: h1_pre = Wf1a * xi, K=128 (A = E region)
        consume<4, ST_WF>(sb, cc, pc, E_OFF, ST_E, 0, acc, true,  wm, wn, lane, tid);
        consume<4, ST_WF>(sb, cc, pc, E_OFF, ST_E, 4, acc, false, wm, wn, lane, tid);

        // f2: qv = bf2 + sum_c lrelu(h1_pre + p + bf1) * wf2
        // F2 partials live in X region (unused in pass 2).
        {
            const char* psrc = g_pscr + ((size_t)tile * 8 + a) * 16384;
            float part[4];
#pragma unroll
            for (int i = 0; i < 4; i++) part[i] = 0.f;
            const float* b1a = bf1 + a * 128;
            const float* w2a = wf2 + a * 128;
#pragma unroll
            for (int im = 0; im < 2; im++)
#pragma unroll
                for (int in = 0; in < 4; in++) {
                    int c = wn * 32 + in * 8 + t4 * 2;
                    int r0 = wm * 32 + im * 16 + g;
                    float2 pa = uph(__ldg((const uint32_t*)(psrc + ((size_t)r0 * 128 + c) * 2)));
                    float2 pb = uph(__ldg((const uint32_t*)(psrc + ((size_t)(r0 + 8) * 128 + c) * 2)));
                    float b0 = __ldg(b1a + c), b1 = __ldg(b1a + c + 1);
                    float w0 = __ldg(w2a + c), w1 = __ldg(w2a + c + 1);
                    part[im * 2 + 0] += lrelu(acc[im][in][0] + pa.x + b0) * w0
                                      + lrelu(acc[im][in][1] + pa.y + b1) * w1;
                    part[im * 2 + 1] += lrelu(acc[im][in][2] + pb.x + b0) * w0
                                      + lrelu(acc[im][in][3] + pb.y + b1) * w1;
                }
#pragma unroll
            for (int i = 0; i < 4; i++) {
                part[i] += __shfl_xor_sync(0xffffffffu, part[i], 1);
                part[i] += __shfl_xor_sync(0xffffffffu, part[i], 2);
            }
            if (t4 == 0) {
#pragma unroll
                for (int i = 0; i < 4; i++) {
                    int row = wm * 32 + (i >> 1) * 16 + g + (i & 1) * 8;
                    ((float*)sm)[row * 4 + wn] = part[i];
                }
            }
            __syncthreads();
            if (tid < 64) {
                const float* bp = (const float*)sm + tid * 4;
                float qv = __ldg(bf2 + a) + bp[0] + bp[1] + bp[2] + bp[3];
                out[(size_t)a * 65536 + (size_t)tile * 64 + tid] = qv;
            }
        }
    }
}

// ------------------------------------------------------------------ launcher
extern "C" void kernel_launch(void* const* d_in, const int* in_sizes, int n_in,
                              void* d_out, int out_size) {
    const float* obs = (const float*)d_in[0];
    const float* act = (const float*)d_in[1];
    const float* Wg  = (const float*)d_in[2];
    const float* bg  = (const float*)d_in[3];
    // d_in[4]=Wq, d_in[5]=Wk: dead (softmax over size-1 axis == 1)
    const float* Wv  = (const float*)d_in[6];
    const float* bv  = (const float*)d_in[7];
    const float* Wf1 = (const float*)d_in[8];
    const float* bf1 = (const float*)d_in[9];
    const float* Wf2 = (const float*)d_in[10];
    const float* bf2 = (const float*)d_in[11];
    float* out = (float*)d_out;

    cudaFuncSetAttribute(critic_main, cudaFuncAttributeMaxDynamicSharedMemorySize,
                         SMEM_TOTAL);
    prep_kernel<<<(NPREP + 255) / 256, 256>>>(Wg, Wv, Wf1);
    critic_main<<<1024, 256, SMEM_TOTAL>>>(obs, act, bg, bv, bf1, Wf2, bf2, out);
}

// round 15
// speedup vs baseline: 3.0002x; 1.2400x over previous
#include <cuda_runtime.h>
#include <cuda_fp16.h>
#include <cstdint>
#include <cstddef>

// smem layout (bytes, base-relative), Bt = 64 batch rows per CTA
//  X region: 0 .. 21504       x image (ST_X, fp16); F2 partial buffer in pass 2
//  E region: 21504 .. 38912   e (pass1) / xi (pass2) image (ST_E, fp16)
//  CB0/1/2:  38912 + {0,1,2}*18432  weight chunk slots (fp16, 128 rows x <=64 kcols)
#define E_OFF   21504u
#define CB0_OFF 38912u
#define SMEM_TOTAL 94208
#define ST_X 336      // x row stride bytes (168 fp16; 160 data)
#define ST_E 272      // e/xi row stride bytes (136 fp16)
#define ST_WF 144     // full weight chunk row stride (72 fp16; 64 data)
#define ST_WH 80      // half weight chunk row stride (40 fp16; 32 data)
#define NCHUNKS 72    // pass1: 8*(2 wg + 1 wg-half + 2 wv + 2 f1b) = 56 ; pass2: 8*2 f1a = 16
#define FULL_B 18432  // 128 * 144
#define HALF_B 10240  // 128 * 80

// ---------------------------------------------------------------- helpers
__device__ __forceinline__ uint32_t smem_to_u32(const void* p) {
    uint32_t a;
    asm("{ .reg .u64 t; cvta.to.shared.u64 t, %1; cvt.u32.u64 %0, t; }"
        : "=r"(a) : "l"(p));
    return a;
}
__device__ __forceinline__ float lrelu(float x) { return x > 0.f ? x : 0.01f * x; }
__device__ __forceinline__ uint32_t pkh(float a, float b) {
    __half2 t = __floats2half2_rn(a, b);
    return *reinterpret_cast<uint32_t*>(&t);
}
__device__ __forceinline__ float2 uph(uint32_t u) {
    __half2 h = *reinterpret_cast<__half2*>(&u);
    return __half22float2(h);
}

#define LDSM4(r, a) \
    asm volatile("ldmatrix.sync.aligned.m8n8.x4.shared.b16 {%0,%1,%2,%3}, [%4];" \
        : "=r"((r)[0]), "=r"((r)[1]), "=r"((r)[2]), "=r"((r)[3]) : "r"(a))

#define MMA(c, av, b0, b1) \
    asm volatile("mma.sync.aligned.m16n8k16.row.col.f32.f16.f16.f32 " \
        "{%0,%1,%2,%3},{%4,%5,%6,%7},{%8,%9},{%0,%1,%2,%3};" \
        : "+f"((c)[0]), "+f"((c)[1]), "+f"((c)[2]), "+f"((c)[3]) \
        : "r"((av)[0]), "r"((av)[1]), "r"((av)[2]), "r"((av)[3]), "r"(b0), "r"(b1))

#define CPWAIT1() asm volatile("cp.async.wait_group 1;" ::: "memory")
#define CPWAIT0() asm volatile("cp.async.wait_group 0;" ::: "memory")
#define CPCOMMIT() asm volatile("cp.async.commit_group;" ::: "memory")

// ------------------------------------------------------------------- scratch
__device__ __align__(16) char g_wg[8 * 47104];      // per agent: full,full,half
__device__ __align__(16) char g_wv[36864];          // 2 full
__device__ __align__(16) char g_wf1[8 * 73728];     // per agent: f1a 2 full | f1b 2 full
// v/p scratch: thread-private fragment layout, 16 KB per (tile, agent):
//   uint4 index = (wid*4 + j)*32 + lane   (j = 0..3, 4 uint4 = 32 fp16 per thread)
// Same thread writes (pass 1) and reads (pass 2) -> any bijection is valid;
// this one makes every STG/LDG.128 a contiguous 512 B per warp.
__device__ __align__(16) char g_vscr[134217728];    // 1024 tiles x 8 agents x 16384 (fp16 v)
__device__ __align__(16) char g_pscr[134217728];    // 1024 tiles x 8 agents x 16384 (fp16 p)

// --------------------------------------------------------------- prep kernel
#define NWG (8 * 160 * 128)
#define NWV (128 * 128)
#define NWF (8 * 256 * 128)
#define NPREP (NWG + NWV + NWF)

__global__ void prep_kernel(const float* __restrict__ Wg,
                            const float* __restrict__ Wv,
                            const float* __restrict__ Wf1) {
    int i = blockIdx.x * blockDim.x + threadIdx.x;
    if (i >= NPREP) return;
    float v; char* base; int n, k, kk, str;
    if (i < NWG) {
        int a = i / 20480, r = i - a * 20480;
        k = r >> 7; n = r & 127;
        v = Wg[(size_t)a * 20480 + (size_t)k * 128 + n];
        int c = k >> 6;                          // 0,1,2
        base = g_wg + (size_t)a * 47104 + (size_t)c * FULL_B;
        if (c < 2) { kk = k & 63; str = ST_WF; }
        else       { kk = k - 128; str = ST_WH; }
    } else if (i < NWG + NWV) {
        int t = i - NWG;
        k = t >> 7; n = t & 127;
        v = Wv[(size_t)(n >> 5) * 4096 + (size_t)k * 32 + (n & 31)];
        base = g_wv + (size_t)(k >> 6) * FULL_B;
        kk = k & 63; str = ST_WF;
    } else {
        int t = i - NWG - NWV;
        int a = t >> 15, r = t & 32767;
        int ii = r >> 7; n = r & 127;
        int p = ii >> 7; k = ii & 127;
        v = Wf1[(size_t)a * 32768 + (size_t)ii * 128 + n];
        base = g_wf1 + (size_t)a * 73728 + (size_t)(p * 2 + (k >> 6)) * FULL_B;
        kk = k & 63; str = ST_WF;
    }
    *(__half*)(base + (size_t)n * str + kk * 2) = __float2half_rn(v);
}

// ---------------------------------------------------------- chunk pipeline
// pass1 per agent (7): wg0(F) wg1(F) wg2(H) wv0 wv1 f1b0 f1b1 ; pass2 (2): f1a0 f1a1
__device__ __forceinline__ const char* chunk_src(int i, bool& half) {
    if (i < 56) {
        int a = i / 7, c = i - a * 7;
        half = (c == 2);
        if (c < 3) return g_wg + (size_t)a * 47104 + (size_t)c * FULL_B;
        if (c < 5) return g_wv + (size_t)(c - 3) * FULL_B;
        return g_wf1 + (size_t)a * 73728 + (size_t)(c - 3) * FULL_B;  // f1b = slots 2,3
    }
    half = false;
    int j = i - 56;
    int a = j >> 1, c = j & 1;
    return g_wf1 + (size_t)a * 73728 + (size_t)c * FULL_B;            // f1a = slots 0,1
}

__device__ __forceinline__ void prefetch_chunk(uint32_t sb, int idx, int tid) {
    bool half;
    const char* s0 = chunk_src(idx, half);
    const char* s = s0 + (size_t)tid * 16;
    uint32_t d = sb + CB0_OFF + (uint32_t)(idx % 3) * (uint32_t)FULL_B
               + (uint32_t)tid * 16u;
    if (half) {
        asm volatile("cp.async.cg.shared.global [%0], [%1], 16;"
                     :: "r"(d), "l"(s) : "memory");
        asm volatile("cp.async.cg.shared.global [%0], [%1], 16;"
                     :: "r"(d + 4096u), "l"(s + 4096) : "memory");
        if (tid < 128)
            asm volatile("cp.async.cg.shared.global [%0], [%1], 16;"
                         :: "r"(d + 8192u), "l"(s + 8192) : "memory");
    } else {
#pragma unroll
        for (int i = 0; i < 4; i++)
            asm volatile("cp.async.cg.shared.global [%0], [%1], 16;"
                         :: "r"(d + (uint32_t)i * 4096u), "l"(s + (size_t)i * 4096)
                         : "memory");
        if (tid < 128)
            asm volatile("cp.async.cg.shared.global [%0], [%1], 16;"
                         :: "r"(d + 16384u), "l"(s + 16384) : "memory");
    }
    CPCOMMIT();
}

// ------------------------------------------------- warp-tile 32x32 GEMM
template<int NKS, int STW>
__device__ __forceinline__ void gemm_chunk(uint32_t sb, uint32_t aOff, int aStr,
        uint32_t bOff, int kbase, float (&acc)[2][4][4], bool init,
        int wm, int wn, int lane) {
    if (init)
#pragma unroll
        for (int im = 0; im < 2; im++)
#pragma unroll
            for (int in = 0; in < 4; in++)
#pragma unroll
                for (int e = 0; e < 4; e++) acc[im][in][e] = 0.f;
    uint32_t aRow = (uint32_t)(wm * 32 + (lane & 15));
    uint32_t bRow = (uint32_t)(wn * 32 + (lane & 15));
    uint32_t colo = (uint32_t)((lane >> 4) * 16);
    uint32_t aBase0 = sb + aOff + aRow * (uint32_t)aStr + (uint32_t)kbase * 32 + colo;
    uint32_t aBase1 = aBase0 + 16u * (uint32_t)aStr;
    uint32_t bBase0 = sb + bOff + bRow * (uint32_t)STW + colo;
    uint32_t bBase1 = bBase0 + 16u * (uint32_t)STW;
#pragma unroll
    for (int ks = 0; ks < NKS; ks++) {
        uint32_t ah[2][4], bh[2][4];
        LDSM4(ah[0], aBase0 + (uint32_t)ks * 32u);
        LDSM4(ah[1], aBase1 + (uint32_t)ks * 32u);
        LDSM4(bh[0], bBase0 + (uint32_t)ks * 32u);
        LDSM4(bh[1], bBase1 + (uint32_t)ks * 32u);
#pragma unroll
        for (int im = 0; im < 2; im++)
#pragma unroll
            for (int in = 0; in < 4; in++) {
                uint32_t b0h = bh[in >> 1][in & 1], b1h = bh[in >> 1][(in & 1) + 2];
                MMA(acc[im][in], ah[im], b0h, b1h);
            }
    }
}

// triple-buffered: ONE sync per chunk. The sync guarantees all warps finished
// gemm(cc-1), so prefetch into slot (cc+2)%3 == (cc-1)%3 is safe. It also
// bounds warp drift: a laggard can be inside at most consume(cc) itself,
// which is what makes the epilogues below safe without extra barriers.
template<int NKS, int STW>
__device__ __forceinline__ void consume(uint32_t sb, int& cc, int& pc,
        uint32_t aOff, int aStr, int kbase, float (&acc)[2][4][4],
        bool init, int wm, int wn, int lane, int tid) {
    if (pc - cc >= 2) CPWAIT1(); else CPWAIT0();
    __syncthreads();
    uint32_t bOff = CB0_OFF + (uint32_t)(cc % 3) * (uint32_t)FULL_B;
    gemm_chunk<NKS, STW>(sb, aOff, aStr, bOff, kbase, acc, init, wm, wn, lane);
    if (pc < NCHUNKS) { prefetch_chunk(sb, pc, tid); pc++; }
    cc++;
}

// ----------------------------------------------------------------- main
__global__ __launch_bounds__(256, 2)
void critic_main(const float* __restrict__ obs, const float* __restrict__ act,
                 const float* __restrict__ bg, const float* __restrict__ bvv,
                 const float* __restrict__ bf1, const float* __restrict__ wf2,
                 const float* __restrict__ bf2, float* __restrict__ out) {
    extern __shared__ __align__(16) char sm[];
    uint32_t sb = smem_to_u32(sm);
    int tid = threadIdx.x;
    int lane = tid & 31, wid = tid >> 5;
    int wm = wid & 1, wn = wid >> 1;
    int g = lane >> 2, t4 = lane & 3;
    int tile = blockIdx.x;

    float acc[2][4][4];
    float S[2][4][4];

    // cache bv for this thread's column pair
    float bv0[4], bv1[4];
#pragma unroll
    for (int in = 0; in < 4; in++) {
        int c = wn * 32 + in * 8 + t4 * 2;
        bv0[in] = __ldg(bvv + c);
        bv1[in] = __ldg(bvv + c + 1);
    }

    int cc = 0, pc = 0;
    prefetch_chunk(sb, pc, tid); pc++;
    prefetch_chunk(sb, pc, tid); pc++;

    // ============================ PASS 1 ============================
    for (int a = 0; a < 8; a++) {
        // x rows -> X region (fp16). Laggards are in gemm(f1b1 of a-1): read E. Safe.
        {
            int row = tid >> 2, q = tid & 3;
            size_t rb = (size_t)a * 65536 + (size_t)tile * 64 + row;
            const float4* op = (const float4*)(obs + rb * 128) + q * 8;
            const float4* ap = (const float4*)(act + rb * 32) + q * 2;
            char* hb = sm + (size_t)row * ST_X;
#pragma unroll 4
            for (int i = 0; i < 8; i++) {
                float4 f = __ldg(op + i);
                int k = q * 32 + i * 4;
                *(uint2*)(hb + k * 2) = make_uint2(pkh(f.x, f.y), pkh(f.z, f.w));
            }
#pragma unroll
            for (int i = 0; i < 2; i++) {
                float4 f = __ldg(ap + i);
                int k = 128 + q * 8 + i * 4;
                *(uint2*)(hb + k * 2) = make_uint2(pkh(f.x, f.y), pkh(f.z, f.w));
            }
        }
        // g GEMM: K=160 = 2 full + 1 half chunk (A = X region)
        consume<4, ST_WF>(sb, cc, pc, 0u, ST_X, 0, acc, true,  wm, wn, lane, tid);
        consume<4, ST_WF>(sb, cc, pc, 0u, ST_X, 4, acc, false, wm, wn, lane, tid);
        consume<2, ST_WH>(sb, cc, pc, 0u, ST_X, 8, acc, false, wm, wn, lane, tid);

        // e = lrelu(acc + bg) -> E region. Laggards are in gemm(wg2): read X. Safe.
        {
            const float* bga = bg + a * 128;
#pragma unroll
            for (int im = 0; im < 2; im++)
#pragma unroll
                for (int in = 0; in < 4; in++) {
                    int c = wn * 32 + in * 8 + t4 * 2;
                    int r0 = wm * 32 + im * 16 + g;
                    float b0 = __ldg(bga + c), b1 = __ldg(bga + c + 1);
                    *(uint32_t*)(sm + E_OFF + (size_t)r0 * ST_E + c * 2) =
                        pkh(lrelu(acc[im][in][0] + b0), lrelu(acc[im][in][1] + b1));
                    *(uint32_t*)(sm + E_OFF + (size_t)(r0 + 8) * ST_E + c * 2) =
                        pkh(lrelu(acc[im][in][2] + b0), lrelu(acc[im][in][3] + b1));
                }
        }
        // v GEMM: K=128 = 2 full chunks (A = E region)
        consume<4, ST_WF>(sb, cc, pc, E_OFF, ST_E, 0, acc, true,  wm, wn, lane, tid);
        consume<4, ST_WF>(sb, cc, pc, E_OFF, ST_E, 4, acc, false, wm, wn, lane, tid);
        // v = lrelu(acc + bv): accumulate S in regs; v -> scratch, thread-
        // private layout (coalesced 512 B per warp per STG.128)
        {
            uint32_t vv[16];
#pragma unroll
            for (int im = 0; im < 2; im++)
#pragma unroll
                for (int in = 0; in < 4; in++) {
                    float v0 = lrelu(acc[im][in][0] + bv0[in]);
                    float v1 = lrelu(acc[im][in][1] + bv1[in]);
                    float v2 = lrelu(acc[im][in][2] + bv0[in]);
                    float v3 = lrelu(acc[im][in][3] + bv1[in]);
                    if (a == 0) {
                        S[im][in][0] = v0; S[im][in][1] = v1;
                        S[im][in][2] = v2; S[im][in][3] = v3;
                    } else {
                        S[im][in][0] += v0; S[im][in][1] += v1;
                        S[im][in][2] += v2; S[im][in][3] += v3;
                    }
                    vv[(im * 4 + in) * 2 + 0] = pkh(v0, v1);
                    vv[(im * 4 + in) * 2 + 1] = pkh(v2, v3);
                }
            uint4* vdst = (uint4*)(g_vscr + ((size_t)tile * 8 + a) * 16384);
#pragma unroll
            for (int j = 0; j < 4; j++)
                vdst[(wid * 4 + j) * 32 + lane] =
                    make_uint4(vv[j * 4], vv[j * 4 + 1], vv[j * 4 + 2], vv[j * 4 + 3]);
        }
        // p GEMM: p = Wf1b * e, K=128 (A = E region, still resident)
        consume<4, ST_WF>(sb, cc, pc, E_OFF, ST_E, 0, acc, true,  wm, wn, lane, tid);
        consume<4, ST_WF>(sb, cc, pc, E_OFF, ST_E, 4, acc, false, wm, wn, lane, tid);
        // p -> scratch (fp16, thread-private layout)
        {
            uint4* pdst = (uint4*)(g_pscr + ((size_t)tile * 8 + a) * 16384);
#pragma unroll
            for (int j = 0; j < 4; j++) {
                int im = j >> 1, in0 = (j & 1) * 2;
                pdst[(wid * 4 + j) * 32 + lane] = make_uint4(
                    pkh(acc[im][in0][0], acc[im][in0][1]),
                    pkh(acc[im][in0][2], acc[im][in0][3]),
                    pkh(acc[im][in0 + 1][0], acc[im][in0 + 1][1]),
                    pkh(acc[im][in0 + 1][2], acc[im][in0 + 1][3]));
            }
        }
    }

    // ============================ PASS 2 ============================
    for (int a = 0; a < 8; a++) {
        __syncthreads();   // laggards may read E (xi[a-1]) in gemm(f1a1); F2 buf reused
        // xi = S - v -> E region (fp16 image); v from thread-private scratch
        {
            const uint4* vsrc = (const uint4*)(g_vscr + ((size_t)tile * 8 + a) * 16384);
#pragma unroll
            for (int j = 0; j < 4; j++) {
                uint4 t = __ldg(vsrc + (wid * 4 + j) * 32 + lane);
                int im = j >> 1, in0 = (j & 1) * 2;
                // t = {pk(v0,v1) of in0, pk(v2,v3) of in0, pk(v0,v1) of in0+1, pk(v2,v3) of in0+1}
                // NOTE: v layout was [(im*4+in)*2 {+0,+1}] -> j*4.. maps as below
                float2 a0 = uph(t.x), a1 = uph(t.y), b0 = uph(t.z), b1 = uph(t.w);
                int c0 = wn * 32 + in0 * 8 + t4 * 2;
                int c1 = c0 + 8;
                int r0 = wm * 32 + im * 16 + g;
                *(uint32_t*)(sm + E_OFF + (size_t)r0 * ST_E + c0 * 2) =
                    pkh(S[im][in0][0] - a0.x, S[im][in0][1] - a0.y);
                *(uint32_t*)(sm + E_OFF + (size_t)(r0 + 8) * ST_E + c0 * 2) =
                    pkh(S[im][in0][2] - a1.x, S[im][in0][3] - a1.y);
                *(uint32_t*)(sm + E_OFF + (size_t)r0 * ST_E + c1 * 2) =
                    pkh(S[im][in0 + 1][0] - b0.x, S[im][in0 + 1][1] - b0.y);
                *(uint32_t*)(sm + E_OFF + (size_t)(r0 + 8) * ST_E + c1 * 2) =
                    pkh(S[im][in0 + 1][2] - b1.x, S[im][in0 + 1][3] - b1.y);
            }
        }
        // f1a GEMM: h1_pre = Wf1a * xi, K=128 (A = E region)
        consume<4, ST_WF>(sb, cc, pc, E_OFF, ST_E, 0, acc, true,  wm, wn, lane, tid);
        consume<4, ST_WF>(sb, cc, pc, E_OFF, ST_E, 4, acc, false, wm, wn, lane, tid);

        // f2: qv = bf2 + sum_c lrelu(h1_pre + p + bf1) * wf2 ; p from scratch
        {
            const uint4* psrc = (const uint4*)(g_pscr + ((size_t)tile * 8 + a) * 16384);
            float part[4];
#pragma unroll
            for (int i = 0; i < 4; i++) part[i] = 0.f;
            const float* b1a = bf1 + a * 128;
            const float* w2a = wf2 + a * 128;
#pragma unroll
            for (int j = 0; j < 4; j++) {
                uint4 t = __ldg(psrc + (wid * 4 + j) * 32 + lane);
                int im = j >> 1, in0 = (j & 1) * 2;
                float2 pa0 = uph(t.x), pa1 = uph(t.y), pb0 = uph(t.z), pb1 = uph(t.w);
                int c0 = wn * 32 + in0 * 8 + t4 * 2;
                int c1 = c0 + 8;
                float g0 = __ldg(b1a + c0), g1 = __ldg(b1a + c0 + 1);
                float h0 = __ldg(b1a + c1), h1 = __ldg(b1a + c1 + 1);
                float w0 = __ldg(w2a + c0), w1 = __ldg(w2a + c0 + 1);
                float y0 = __ldg(w2a + c1), y1 = __ldg(w2a + c1 + 1);
                part[im * 2 + 0] += lrelu(acc[im][in0][0] + pa0.x + g0) * w0
                                  + lrelu(acc[im][in0][1] + pa0.y + g1) * w1
                                  + lrelu(acc[im][in0 + 1][0] + pb0.x + h0) * y0
                                  + lrelu(acc[im][in0 + 1][1] + pb0.y + h1) * y1;
                part[im * 2 + 1] += lrelu(acc[im][in0][2] + pa1.x + g0) * w0
                                  + lrelu(acc[im][in0][3] + pa1.y + g1) * w1
                                  + lrelu(acc[im][in0 + 1][2] + pb1.x + h0) * y0
                                  + lrelu(acc[im][in0 + 1][3] + pb1.y + h1) * y1;
            }
#pragma unroll
            for (int i = 0; i < 4; i++) {
                part[i] += __shfl_xor_sync(0xffffffffu, part[i], 1);
                part[i] += __shfl_xor_sync(0xffffffffu, part[i], 2);
            }
            if (t4 == 0) {
#pragma unroll
                for (int i = 0; i < 4; i++) {
                    int row = wm * 32 + (i >> 1) * 16 + g + (i & 1) * 8;
                    ((float*)sm)[row * 4 + wn] = part[i];
                }
            }
            __syncthreads();
            if (tid < 64) {
                const float* bp = (const float*)sm + tid * 4;
                float qv = __ldg(bf2 + a) + bp[0] + bp[1] + bp[2] + bp[3];
                out[(size_t)a * 65536 + (size_t)tile * 64 + tid] = qv;
            }
        }
    }
}

// ------------------------------------------------------------------ launcher
extern "C" void kernel_launch(void* const* d_in, const int* in_sizes, int n_in,
                              void* d_out, int out_size) {
    const float* obs = (const float*)d_in[0];
    const float* act = (const float*)d_in[1];
    const float* Wg  = (const float*)d_in[2];
    const float* bg  = (const float*)d_in[3];
    // d_in[4]=Wq, d_in[5]=Wk: dead (softmax over size-1 axis == 1)
    const float* Wv  = (const float*)d_in[6];
    const float* bv  = (const float*)d_in[7];
    const float* Wf1 = (const float*)d_in[8];
    const float* bf1 = (const float*)d_in[9];
    const float* Wf2 = (const float*)d_in[10];
    const float* bf2 = (const float*)d_in[11];
    float* out = (float*)d_out;

    cudaFuncSetAttribute(critic_main, cudaFuncAttributeMaxDynamicSharedMemorySize,
                         SMEM_TOTAL);
    prep_kernel<<<(NPREP + 255) / 256, 256>>>(Wg, Wv, Wf1);
    critic_main<<<1024, 256, SMEM_TOTAL>>>(obs, act, bg, bv, bf1, Wf2, bf2, out);
}

// round 17
// speedup vs baseline: 3.4961x; 1.1653x over previous
#include <cuda_runtime.h>
#include <cuda_fp16.h>
#include <cstdint>
#include <cstddef>

// smem layout (bytes, base-relative), Bt = 64 batch rows per CTA
//  X region: 0 .. 21504       x image (ST_X, fp16); f2 partial buffer in pass 2
//  E region: 21504 .. 38912   e (pass1) / xi (pass2) image (ST_E, fp16)
#define E_OFF   21504u
#define SMEM_TOTAL 38912
#define ST_X 336      // x row stride bytes (168 fp16; 160 data)
#define ST_E 272      // e/xi row stride bytes (136 fp16)

// ---------------------------------------------------------------- helpers
__device__ __forceinline__ uint32_t smem_to_u32(const void* p) {
    uint32_t a;
    asm("{ .reg .u64 t; cvta.to.shared.u64 t, %1; cvt.u32.u64 %0, t; }"
        : "=r"(a) : "l"(p));
    return a;
}
__device__ __forceinline__ float lrelu(float x) { return x > 0.f ? x : 0.01f * x; }
__device__ __forceinline__ uint32_t pkh(float a, float b) {
    __half2 t = __floats2half2_rn(a, b);
    return *reinterpret_cast<uint32_t*>(&t);
}
__device__ __forceinline__ float2 uph(uint32_t u) {
    __half2 h = *reinterpret_cast<__half2*>(&u);
    return __half22float2(h);
}

#define LDSM4(r, a) \
    asm volatile("ldmatrix.sync.aligned.m8n8.x4.shared.b16 {%0,%1,%2,%3}, [%4];" \
        : "=r"((r)[0]), "=r"((r)[1]), "=r"((r)[2]), "=r"((r)[3]) : "r"(a))

#define MMA(c, av, b0, b1) \
    asm volatile("mma.sync.aligned.m16n8k16.row.col.f32.f16.f16.f32 " \
        "{%0,%1,%2,%3},{%4,%5,%6,%7},{%8,%9},{%0,%1,%2,%3};" \
        : "+f"((c)[0]), "+f"((c)[1]), "+f"((c)[2]), "+f"((c)[3]) \
        : "r"((av)[0]), "r"((av)[1]), "r"((av)[2]), "r"((av)[3]), "r"(b0), "r"(b1))

// ------------------------------------------------------------------- scratch
// Weight images in MMA-fragment-packed order:
//   uint4 index = (kb2*16 + ng)*32 + lane ; uint4 = {r0(kb=2*kb2), r1(kb=2*kb2),
//   r0(kb=2*kb2+1), r1(kb=2*kb2+1)} where for frag reg r0/r1 of n8k16:
//   n = ng*8 + (lane>>2), k = kb*16 + (lane&3)*2 (+8 for r1), halves (k, k+1).
// One LDG.128 per lane per ng per k32: 512 B contiguous per warp.
__device__ __align__(16) char g_wg[8 * 40960];      // K=160: kb2 0..4
__device__ __align__(16) char g_wv[32768];          // K=128: kb2 0..3
__device__ __align__(16) char g_wf1[8 * 65536];     // per agent: f1a (32768) | f1b (32768)
// v/p scratch: thread-private fragment layout (same thread writes & reads):
//   uint4 index = (wid*4 + j)*32 + lane  -> coalesced 512 B per warp STG/LDG.128
__device__ __align__(16) char g_vscr[134217728];    // 1024 tiles x 8 agents x 16384 (fp16 v)
__device__ __align__(16) char g_pscr[134217728];    // 1024 tiles x 8 agents x 16384 (fp16 p)

// --------------------------------------------------------------- prep kernel
// One thread per packed uint32 (pair of fp16). Decode packed position -> (n,k).
#define RWG 10240              // uint32 per agent wg image (5 kb2)
#define RWV 8192               // wv image (4 kb2)
#define RWF 8192               // per f1 part (4 kb2)
#define NPREP (8 * RWG + RWV + 16 * RWF)   // 221184

__global__ void prep_kernel(const float* __restrict__ Wg,
                            const float* __restrict__ Wv,
                            const float* __restrict__ Wf1) {
    int i = blockIdx.x * blockDim.x + threadIdx.x;
    if (i >= NPREP) return;
    int r;
    uint32_t* dst;
    const float* s0;
    int sstride;   // source stride between k and k+1
    if (i < 8 * RWG) {
        int a = i / RWG; r = i - a * RWG;
        int lane = (r >> 2) & 31, w = r & 3;
        int ng = (r >> 7) & 15, kb2 = r >> 11;
        int n = ng * 8 + (lane >> 2);
        int kc = (kb2 * 2 + (w >> 1)) * 16 + (lane & 3) * 2 + (w & 1) * 8;
        s0 = Wg + (size_t)a * 20480 + (size_t)kc * 128 + n; sstride = 128;
        dst = (uint32_t*)g_wg + (size_t)a * RWG + r;
    } else if (i < 8 * RWG + RWV) {
        r = i - 8 * RWG;
        int lane = (r >> 2) & 31, w = r & 3;
        int ng = (r >> 7) & 15, kb2 = r >> 11;
        int n = ng * 8 + (lane >> 2);
        int kc = (kb2 * 2 + (w >> 1)) * 16 + (lane & 3) * 2 + (w & 1) * 8;
        s0 = Wv + (size_t)(n >> 5) * 4096 + (size_t)kc * 32 + (n & 31); sstride = 32;
        dst = (uint32_t*)g_wv + r;
    } else {
        int j = i - 8 * RWG - RWV;
        int a = j / (2 * RWF); int r2 = j - a * (2 * RWF);
        int p = r2 >> 13; r = r2 & (RWF - 1);
        int lane = (r >> 2) & 31, w = r & 3;
        int ng = (r >> 7) & 15, kb2 = r >> 11;
        int n = ng * 8 + (lane >> 2);
        int kc = (kb2 * 2 + (w >> 1)) * 16 + (lane & 3) * 2 + (w & 1) * 8;
        int ii = p * 128 + kc;
        s0 = Wf1 + (size_t)a * 32768 + (size_t)ii * 128 + n; sstride = 128;
        dst = (uint32_t*)g_wf1 + (size_t)a * 16384 + (size_t)p * RWF + r;
    }
    *dst = pkh(s0[0], s0[sstride]);
}

// ------------------------------------------- GEMM: A via LDSM, B via LDG
// Warp tile 32x32 of C[64][128]; B double-buffered in registers (latency hiding).
template<int NKB2>
__device__ __forceinline__ void gemm_ldg(uint32_t sb, uint32_t aOff, int aStr,
        const uint4* __restrict__ bbase, float (&acc)[2][4][4], bool init,
        int wm, int wn, int lane) {
    if (init)
#pragma unroll
        for (int im = 0; im < 2; im++)
#pragma unroll
            for (int in = 0; in < 4; in++)
#pragma unroll
                for (int e = 0; e < 4; e++) acc[im][in][e] = 0.f;
    uint32_t aRow = (uint32_t)(wm * 32 + (lane & 15));
    uint32_t colo = (uint32_t)((lane >> 4) * 16);
    uint32_t aBase0 = sb + aOff + aRow * (uint32_t)aStr + colo;
    uint32_t aBase1 = aBase0 + 16u * (uint32_t)aStr;
    const uint4* bp = bbase + (size_t)(wn * 4) * 32 + lane;
    uint4 bq[2][4];
#pragma unroll
    for (int ngp = 0; ngp < 4; ngp++) bq[0][ngp] = __ldg(bp + ngp * 32);
#pragma unroll
    for (int kb2 = 0; kb2 < NKB2; kb2++) {
        int cur = kb2 & 1;
        if (kb2 + 1 < NKB2) {
#pragma unroll
            for (int ngp = 0; ngp < 4; ngp++)
                bq[cur ^ 1][ngp] = __ldg(bp + (size_t)(kb2 + 1) * 512 + ngp * 32);
        }
#pragma unroll
        for (int h = 0; h < 2; h++) {
            uint32_t co = (uint32_t)(kb2 * 2 + h) * 32u;
            uint32_t ah[2][4];
            LDSM4(ah[0], aBase0 + co);
            LDSM4(ah[1], aBase1 + co);
#pragma unroll
            for (int ngp = 0; ngp < 4; ngp++) {
                uint32_t b0 = h ? bq[cur][ngp].z : bq[cur][ngp].x;
                uint32_t b1 = h ? bq[cur][ngp].w : bq[cur][ngp].y;
                MMA(acc[0][ngp], ah[0], b0, b1);
                MMA(acc[1][ngp], ah[1], b0, b1);
            }
        }
    }
}

// ----------------------------------------------------------------- main
__global__ __launch_bounds__(256, 2)
void critic_main(const float* __restrict__ obs, const float* __restrict__ act,
                 const float* __restrict__ bg, const float* __restrict__ bvv,
                 const float* __restrict__ bf1, const float* __restrict__ wf2,
                 const float* __restrict__ bf2, float* __restrict__ out) {
    extern __shared__ __align__(16) char sm[];
    uint32_t sb = smem_to_u32(sm);
    int tid = threadIdx.x;
    int lane = tid & 31, wid = tid >> 5;
    int wm = wid & 1, wn = wid >> 1;
    int g = lane >> 2, t4 = lane & 3;
    int tile = blockIdx.x;

    float acc[2][4][4];
    float S[2][4][4];

    float bv0[4], bv1[4];
#pragma unroll
    for (int in = 0; in < 4; in++) {
        int c = wn * 32 + in * 8 + t4 * 2;
        bv0[in] = __ldg(bvv + c);
        bv1[in] = __ldg(bvv + c + 1);
    }

    // ============================ PASS 1 ============================
    for (int a = 0; a < 8; a++) {
        // x rows -> X region. Warp-per-row: one LDG.128 sweep, fully coalesced.
        // Laggards are in p-gemm of a-1 (reads E) -> X write is safe.
        {
            size_t rb = (size_t)a * 65536 + (size_t)tile * 64;
#pragma unroll
            for (int i = 0; i < 8; i++) {
                int row = wid + i * 8;
                float4 f = __ldg((const float4*)(obs + (rb + row) * 128) + lane);
                *(uint2*)(sm + (size_t)row * ST_X + lane * 8) =
                    make_uint2(pkh(f.x, f.y), pkh(f.z, f.w));
            }
            int lf = tid & 7;
#pragma unroll
            for (int j = 0; j < 2; j++) {
                int row = (tid >> 3) + j * 32;
                float4 f = __ldg((const float4*)(act + (rb + row) * 32) + lf);
                *(uint2*)(sm + (size_t)row * ST_X + 256 + lf * 8) =
                    make_uint2(pkh(f.x, f.y), pkh(f.z, f.w));
            }
        }
        __syncthreads();   // all x writes visible before g-gemm reads X
        // g GEMM: K=160 (A = X)
        gemm_ldg<5>(sb, 0u, ST_X, (const uint4*)(g_wg + (size_t)a * 40960),
                    acc, true, wm, wn, lane);
        // e = lrelu(acc + bg) -> E region (laggards in g-gemm read X only)
        {
            const float* bga = bg + a * 128;
#pragma unroll
            for (int im = 0; im < 2; im++)
#pragma unroll
                for (int in = 0; in < 4; in++) {
                    int c = wn * 32 + in * 8 + t4 * 2;
                    int r0 = wm * 32 + im * 16 + g;
                    float b0 = __ldg(bga + c), b1 = __ldg(bga + c + 1);
                    *(uint32_t*)(sm + E_OFF + (size_t)r0 * ST_E + c * 2) =
                        pkh(lrelu(acc[im][in][0] + b0), lrelu(acc[im][in][1] + b1));
                    *(uint32_t*)(sm + E_OFF + (size_t)(r0 + 8) * ST_E + c * 2) =
                        pkh(lrelu(acc[im][in][2] + b0), lrelu(acc[im][in][3] + b1));
                }
        }
        __syncthreads();   // all e writes visible before v-gemm reads E
        // v GEMM: K=128 (A = E)
        gemm_ldg<4>(sb, E_OFF, ST_E, (const uint4*)g_wv, acc, true, wm, wn, lane);
        // v = lrelu(acc + bv): accumulate S in regs; v -> coalesced scratch
        {
            uint32_t vv[16];
#pragma unroll
            for (int im = 0; im < 2; im++)
#pragma unroll
                for (int in = 0; in < 4; in++) {
                    float v0 = lrelu(acc[im][in][0] + bv0[in]);
                    float v1 = lrelu(acc[im][in][1] + bv1[in]);
                    float v2 = lrelu(acc[im][in][2] + bv0[in]);
                    float v3 = lrelu(acc[im][in][3] + bv1[in]);
                    if (a == 0) {
                        S[im][in][0] = v0; S[im][in][1] = v1;
                        S[im][in][2] = v2; S[im][in][3] = v3;
                    } else {
                        S[im][in][0] += v0; S[im][in][1] += v1;
                        S[im][in][2] += v2; S[im][in][3] += v3;
                    }
                    vv[(im * 4 + in) * 2 + 0] = pkh(v0, v1);
                    vv[(im * 4 + in) * 2 + 1] = pkh(v2, v3);
                }
            uint4* vdst = (uint4*)(g_vscr + ((size_t)tile * 8 + a) * 16384);
#pragma unroll
            for (int j = 0; j < 4; j++)
                vdst[(wid * 4 + j) * 32 + lane] =
                    make_uint4(vv[j * 4], vv[j * 4 + 1], vv[j * 4 + 2], vv[j * 4 + 3]);
        }
        // p GEMM: p = Wf1b * e, K=128 (A = E, unchanged; no barrier needed)
        gemm_ldg<4>(sb, E_OFF, ST_E,
                    (const uint4*)(g_wf1 + (size_t)a * 65536 + 32768),
                    acc, true, wm, wn, lane);
        // p -> coalesced scratch (fp16)
        {
            uint4* pdst = (uint4*)(g_pscr + ((size_t)tile * 8 + a) * 16384);
#pragma unroll
            for (int j = 0; j < 4; j++) {
                int im = j >> 1, in0 = (j & 1) * 2;
                pdst[(wid * 4 + j) * 32 + lane] = make_uint4(
                    pkh(acc[im][in0][0], acc[im][in0][1]),
                    pkh(acc[im][in0][2], acc[im][in0][3]),
                    pkh(acc[im][in0 + 1][0], acc[im][in0 + 1][1]),
                    pkh(acc[im][in0 + 1][2], acc[im][in0 + 1][3]));
            }
        }
    }

    // ============================ PASS 2 ============================
    for (int a = 0; a < 8; a++) {
        __syncthreads();   // laggards may read E (p-gemm a7 / f1a of a-1); f2 buf reuse
        // xi = S - v -> E region; v from thread-private scratch
        {
            const uint4* vsrc = (const uint4*)(g_vscr + ((size_t)tile * 8 + a) * 16384);
#pragma unroll
            for (int j = 0; j < 4; j++) {
                uint4 t = __ldg(vsrc + (wid * 4 + j) * 32 + lane);
                int im = j >> 1, in0 = (j & 1) * 2;
                float2 a0 = uph(t.x), a1 = uph(t.y), b0 = uph(t.z), b1 = uph(t.w);
                int c0 = wn * 32 + in0 * 8 + t4 * 2;
                int c1 = c0 + 8;
                int r0 = wm * 32 + im * 16 + g;
                *(uint32_t*)(sm + E_OFF + (size_t)r0 * ST_E + c0 * 2) =
                    pkh(S[im][in0][0] - a0.x, S[im][in0][1] - a0.y);
                *(uint32_t*)(sm + E_OFF + (size_t)(r0 + 8) * ST_E + c0 * 2) =
                    pkh(S[im][in0][2] - a1.x, S[im][in0][3] - a1.y);
                *(uint32_t*)(sm + E_OFF + (size_t)r0 * ST_E + c1 * 2) =
                    pkh(S[im][in0 + 1][0] - b0.x, S[im][in0 + 1][1] - b0.y);
                *(uint32_t*)(sm + E_OFF + (size_t)(r0 + 8) * ST_E + c1 * 2) =
                    pkh(S[im][in0 + 1][2] - b1.x, S[im][in0 + 1][3] - b1.y);
            }
        }
        __syncthreads();   // all xi writes visible before f1a-gemm reads E
        // f1a GEMM: h1_pre = Wf1a * xi, K=128
        gemm_ldg<4>(sb, E_OFF, ST_E, (const uint4*)(g_wf1 + (size_t)a * 65536),
                    acc, true, wm, wn, lane);

        // f2: qv = bf2 + sum_c lrelu(h1_pre + p + bf1) * wf2 ; p from scratch
        {
            const uint4* psrc = (const uint4*)(g_pscr + ((size_t)tile * 8 + a) * 16384);
            float part[4];
#pragma unroll
            for (int i = 0; i < 4; i++) part[i] = 0.f;
            const float* b1a = bf1 + a * 128;
            const float* w2a = wf2 + a * 128;
#pragma unroll
            for (int j = 0; j < 4; j++) {
                uint4 t = __ldg(psrc + (wid * 4 + j) * 32 + lane);
                int im = j >> 1, in0 = (j & 1) * 2;
                float2 pa0 = uph(t.x), pa1 = uph(t.y), pb0 = uph(t.z), pb1 = uph(t.w);
                int c0 = wn * 32 + in0 * 8 + t4 * 2;
                int c1 = c0 + 8;
                float g0 = __ldg(b1a + c0), g1 = __ldg(b1a + c0 + 1);
                float h0 = __ldg(b1a + c1), h1 = __ldg(b1a + c1 + 1);
                float w0 = __ldg(w2a + c0), w1 = __ldg(w2a + c0 + 1);
                float y0 = __ldg(w2a + c1), y1 = __ldg(w2a + c1 + 1);
                part[im * 2 + 0] += lrelu(acc[im][in0][0] + pa0.x + g0) * w0
                                  + lrelu(acc[im][in0][1] + pa0.y + g1) * w1
                                  + lrelu(acc[im][in0 + 1][0] + pb0.x + h0) * y0
                                  + lrelu(acc[im][in0 + 1][1] + pb0.y + h1) * y1;
                part[im * 2 + 1] += lrelu(acc[im][in0][2] + pa1.x + g0) * w0
                                  + lrelu(acc[im][in0][3] + pa1.y + g1) * w1
                                  + lrelu(acc[im][in0 + 1][2] + pb1.x + h0) * y0
                                  + lrelu(acc[im][in0 + 1][3] + pb1.y + h1) * y1;
            }
#pragma unroll
            for (int i = 0; i < 4; i++) {
                part[i] += __shfl_xor_sync(0xffffffffu, part[i], 1);
                part[i] += __shfl_xor_sync(0xffffffffu, part[i], 2);
            }
            if (t4 == 0) {
#pragma unroll
                for (int i = 0; i < 4; i++) {
                    int row = wm * 32 + (i >> 1) * 16 + g + (i & 1) * 8;
                    ((float*)sm)[row * 4 + wn] = part[i];
                }
            }
            __syncthreads();
            if (tid < 64) {
                const float* bp = (const float*)sm + tid * 4;
                float qv = __ldg(bf2 + a) + bp[0] + bp[1] + bp[2] + bp[3];
                out[(size_t)a * 65536 + (size_t)tile * 64 + tid] = qv;
            }
        }
    }
}

// ------------------------------------------------------------------ launcher
extern "C" void kernel_launch(void* const* d_in, const int* in_sizes, int n_in,
                              void* d_out, int out_size) {
    const float* obs = (const float*)d_in[0];
    const float* act = (const float*)d_in[1];
    const float* Wg  = (const float*)d_in[2];
    const float* bg  = (const float*)d_in[3];
    // d_in[4]=Wq, d_in[5]=Wk: dead (softmax over size-1 axis == 1)
    const float* Wv  = (const float*)d_in[6];
    const float* bv  = (const float*)d_in[7];
    const float* Wf1 = (const float*)d_in[8];
    const float* bf1 = (const float*)d_in[9];
    const float* Wf2 = (const float*)d_in[10];
    const float* bf2 = (const float*)d_in[11];
    float* out = (float*)d_out;

    cudaFuncSetAttribute(critic_main, cudaFuncAttributeMaxDynamicSharedMemorySize,
                         SMEM_TOTAL);
    // small smem footprint -> maximize L1 cache carveout for weight LDGs
    cudaFuncSetAttribute(critic_main, cudaFuncAttributePreferredSharedMemoryCarveout, 40);
    prep_kernel<<<(NPREP + 255) / 256, 256>>>(Wg, Wv, Wf1);
    critic_main<<<1024, 256, SMEM_TOTAL>>>(obs, act, bg, bv, bf1, Wf2, bf2, out);
}